// round 1
// baseline (speedup 1.0000x reference)
#include <cuda_runtime.h>
#include <math.h>

#define N_ADDR 150000
#define N_TX   200000
#define HID    32
#define HEADS  4
#define E_AT   1000000
#define E_TA   1000000
#define E_AA   500000

// ---------------- scratch (device globals; no allocations allowed) ----------------
__device__ float g_ha[(size_t)N_ADDR * HID];   // projected addr features (per layer)
__device__ float g_ht[(size_t)N_TX * HID];     // projected tx features
__device__ float g_a [(size_t)N_ADDR * HID];   // addr features between layers
__device__ float g_t [(size_t)N_TX * HID];     // tx features between layers

__device__ float g_otx[(size_t)N_TX * HID];    // relation accumulators
__device__ float g_oa1[(size_t)N_ADDR * HID];
__device__ float g_oa2[(size_t)N_ADDR * HID];

__device__ float g_asA0[(size_t)N_ADDR * HEADS]; // alpha_src addr, edge type 0 (a->t)
__device__ float g_asA2[(size_t)N_ADDR * HEADS]; // alpha_src addr, edge type 2 (a->a)
__device__ float g_adA1[(size_t)N_ADDR * HEADS]; // alpha_dst addr, edge type 1 (t->a)
__device__ float g_adA2[(size_t)N_ADDR * HEADS]; // alpha_dst addr, edge type 2 (a->a)
__device__ float g_asT [(size_t)N_TX * HEADS];   // alpha_src tx, edge type 1
__device__ float g_adT [(size_t)N_TX * HEADS];   // alpha_dst tx, edge type 0

__device__ unsigned g_m_tx[(size_t)N_TX * HEADS];   // segment-max keys
__device__ unsigned g_m_a1[(size_t)N_ADDR * HEADS];
__device__ unsigned g_m_a2[(size_t)N_ADDR * HEADS];
__device__ float    g_s_tx[(size_t)N_TX * HEADS];   // segment exp-sums
__device__ float    g_s_a1[(size_t)N_ADDR * HEADS];
__device__ float    g_s_a2[(size_t)N_ADDR * HEADS];

__device__ float g_sem[2 * HID];  // semantic accumulators (sum of tanh over nodes)
__device__ float g_attn[2];       // semantic attention weights

// ---------------- helpers ----------------
__device__ __forceinline__ unsigned fenc(float x) {
    unsigned b = __float_as_uint(x);
    return (b & 0x80000000u) ? ~b : (b | 0x80000000u);
}
__device__ __forceinline__ float fdec(unsigned u) {
    return (u & 0x80000000u) ? __uint_as_float(u & 0x7FFFFFFFu)
                             : __uint_as_float(~u);
}
__device__ __forceinline__ float lrelu(float l) { return l >= 0.f ? l : 0.2f * l; }

static inline int cdiv(int a, int b) { return (a + b - 1) / b; }

// ---------------- kernels ----------------

// zero all per-layer accumulators
__global__ void k_clear() {
    size_t stride = (size_t)gridDim.x * blockDim.x;
    for (size_t i = (size_t)blockIdx.x * blockDim.x + threadIdx.x;
         i < (size_t)N_TX * HID; i += stride) {
        g_otx[i] = 0.f;
        if (i < (size_t)N_ADDR * HID) { g_oa1[i] = 0.f; g_oa2[i] = 0.f; }
        if (i < (size_t)N_TX * HEADS) { g_m_tx[i] = 0u; g_s_tx[i] = 0.f; }
        if (i < (size_t)N_ADDR * HEADS) {
            g_m_a1[i] = 0u; g_s_a1[i] = 0.f;
            g_m_a2[i] = 0u; g_s_a2[i] = 0.f;
        }
        if (i < 2 * HID) g_sem[i] = 0.f;
    }
}

// out[n,c] = x[n,:] @ W[:,c] + b[c]   (thread per output element)
__global__ void k_proj(const float* __restrict__ xext, int useExt, int isAddr,
                       const float* __restrict__ W, const float* __restrict__ b,
                       int N, int F) {
    __shared__ float sW[64 * HID];
    __shared__ float sb[HID];
    for (int i = threadIdx.x; i < F * HID; i += blockDim.x) sW[i] = W[i];
    if (threadIdx.x < HID) sb[threadIdx.x] = b[threadIdx.x];
    __syncthreads();

    const float* x = useExt ? xext : (isAddr ? (const float*)g_a : (const float*)g_t);
    float* outp = isAddr ? g_ha : g_ht;

    int idx = blockIdx.x * blockDim.x + threadIdx.x;
    int n = idx >> 5, c = idx & 31;
    if (n >= N) return;
    const float* xr = x + (size_t)n * F;
    float acc = sb[c];
    for (int k = 0; k < F; k++) acc += xr[k] * sW[k * HID + c];
    outp[(size_t)n * HID + c] = acc;
}

// node-level attention dot products for addr nodes (4 relevant att vectors)
__global__ void k_alpha_addr(const float* __restrict__ as_l, const float* __restrict__ ad_l) {
    __shared__ float v0[32], v2[32], d1[32], d2[32];
    int tid = threadIdx.x;
    if (tid < 32) {
        v0[tid] = as_l[tid];        // att_src edge 0
        v2[tid] = as_l[64 + tid];   // att_src edge 2
        d1[tid] = ad_l[32 + tid];   // att_dst edge 1
        d2[tid] = ad_l[64 + tid];   // att_dst edge 2
    }
    __syncthreads();
    int n = blockIdx.x * blockDim.x + tid;
    if (n >= N_ADDR) return;
    const float4* hp = (const float4*)(g_ha + (size_t)n * HID);
    float x[32];
#pragma unroll
    for (int i = 0; i < 8; i++) {
        float4 v = hp[i];
        x[4 * i] = v.x; x[4 * i + 1] = v.y; x[4 * i + 2] = v.z; x[4 * i + 3] = v.w;
    }
    float r0[4], r2[4], s1[4], s2[4];
#pragma unroll
    for (int h = 0; h < 4; h++) {
        float a0 = 0.f, a2 = 0.f, b1 = 0.f, b2 = 0.f;
#pragma unroll
        for (int d = 0; d < 8; d++) {
            int i = h * 8 + d;
            a0 += x[i] * v0[i]; a2 += x[i] * v2[i];
            b1 += x[i] * d1[i]; b2 += x[i] * d2[i];
        }
        r0[h] = a0; r2[h] = a2; s1[h] = b1; s2[h] = b2;
    }
    *(float4*)(g_asA0 + (size_t)n * 4) = make_float4(r0[0], r0[1], r0[2], r0[3]);
    *(float4*)(g_asA2 + (size_t)n * 4) = make_float4(r2[0], r2[1], r2[2], r2[3]);
    *(float4*)(g_adA1 + (size_t)n * 4) = make_float4(s1[0], s1[1], s1[2], s1[3]);
    *(float4*)(g_adA2 + (size_t)n * 4) = make_float4(s2[0], s2[1], s2[2], s2[3]);
}

// node-level attention dot products for tx nodes (2 relevant att vectors)
__global__ void k_alpha_tx(const float* __restrict__ as_l, const float* __restrict__ ad_l) {
    __shared__ float v1[32], d0[32];
    int tid = threadIdx.x;
    if (tid < 32) {
        v1[tid] = as_l[32 + tid];   // att_src edge 1
        d0[tid] = ad_l[tid];        // att_dst edge 0
    }
    __syncthreads();
    int n = blockIdx.x * blockDim.x + tid;
    if (n >= N_TX) return;
    const float4* hp = (const float4*)(g_ht + (size_t)n * HID);
    float x[32];
#pragma unroll
    for (int i = 0; i < 8; i++) {
        float4 v = hp[i];
        x[4 * i] = v.x; x[4 * i + 1] = v.y; x[4 * i + 2] = v.z; x[4 * i + 3] = v.w;
    }
    float rs[4], rd[4];
#pragma unroll
    for (int h = 0; h < 4; h++) {
        float a = 0.f, b = 0.f;
#pragma unroll
        for (int d = 0; d < 8; d++) {
            int i = h * 8 + d;
            a += x[i] * v1[i]; b += x[i] * d0[i];
        }
        rs[h] = a; rd[h] = b;
    }
    *(float4*)(g_asT + (size_t)n * 4) = make_float4(rs[0], rs[1], rs[2], rs[3]);
    *(float4*)(g_adT + (size_t)n * 4) = make_float4(rd[0], rd[1], rd[2], rd[3]);
}

// pass 1: segment max over leaky-relu logits (order-preserving uint atomicMax)
__global__ void k_edge_max(int rel, const int* __restrict__ src,
                           const int* __restrict__ dst, int E) {
    const float* as_; const float* ad_; unsigned* mk;
    if (rel == 0)      { as_ = g_asA0; ad_ = g_adT;  mk = g_m_tx; }
    else if (rel == 1) { as_ = g_asT;  ad_ = g_adA1; mk = g_m_a1; }
    else               { as_ = g_asA2; ad_ = g_adA2; mk = g_m_a2; }
    int e = blockIdx.x * blockDim.x + threadIdx.x;
    if (e >= E) return;
    int s = src[e], d = dst[e];
    float4 av = *(const float4*)(as_ + (size_t)s * 4);
    float4 bv = *(const float4*)(ad_ + (size_t)d * 4);
    float L[4] = { av.x + bv.x, av.y + bv.y, av.z + bv.z, av.w + bv.w };
    unsigned* mrow = mk + (size_t)d * 4;
#pragma unroll
    for (int h = 0; h < 4; h++) atomicMax(&mrow[h], fenc(lrelu(L[h])));
}

// pass 2: w = exp(logit - max); accumulate exp-sum and unnormalized messages
__global__ void k_edge_acc(int rel, const int* __restrict__ src,
                           const int* __restrict__ dst, int E) {
    const float* as_; const float* ad_; const unsigned* mk;
    float* ss; const float* hs; float* oa;
    if (rel == 0)      { as_ = g_asA0; ad_ = g_adT;  mk = g_m_tx; ss = g_s_tx; hs = g_ha; oa = g_otx; }
    else if (rel == 1) { as_ = g_asT;  ad_ = g_adA1; mk = g_m_a1; ss = g_s_a1; hs = g_ht; oa = g_oa1; }
    else               { as_ = g_asA2; ad_ = g_adA2; mk = g_m_a2; ss = g_s_a2; hs = g_ha; oa = g_oa2; }
    int e = blockIdx.x * blockDim.x + threadIdx.x;
    if (e >= E) return;
    int s = src[e], d = dst[e];
    float4 av = *(const float4*)(as_ + (size_t)s * 4);
    float4 bv = *(const float4*)(ad_ + (size_t)d * 4);
    float L[4] = { av.x + bv.x, av.y + bv.y, av.z + bv.z, av.w + bv.w };
    const unsigned* mrow = mk + (size_t)d * 4;
    float* srow = ss + (size_t)d * 4;
    const float4* hp = (const float4*)(hs + (size_t)s * HID);
    float* orow = oa + (size_t)d * HID;
#pragma unroll
    for (int h = 0; h < 4; h++) {
        float w = __expf(lrelu(L[h]) - fdec(mrow[h]));
        atomicAdd(&srow[h], w);
        float4 v0 = hp[2 * h], v1 = hp[2 * h + 1];
        float* ob = orow + 8 * h;
        atomicAdd(ob + 0, w * v0.x); atomicAdd(ob + 1, w * v0.y);
        atomicAdd(ob + 2, w * v0.z); atomicAdd(ob + 3, w * v0.w);
        atomicAdd(ob + 4, w * v1.x); atomicAdd(ob + 5, w * v1.y);
        atomicAdd(ob + 6, w * v1.z); atomicAdd(ob + 7, w * v1.w);
    }
}

// normalize by exp-sum + relu; rel 0 writes new tx features directly
__global__ void k_finalize(int rel) {
    const float* acc; const float* ss; float* outp; int N;
    if (rel == 0)      { acc = g_otx; ss = g_s_tx; outp = g_t;   N = N_TX; }
    else if (rel == 1) { acc = g_oa1; ss = g_s_a1; outp = g_oa1; N = N_ADDR; }
    else               { acc = g_oa2; ss = g_s_a2; outp = g_oa2; N = N_ADDR; }
    int idx = blockIdx.x * blockDim.x + threadIdx.x;
    if (idx >= N * HID) return;
    int n = idx >> 5, c = idx & 31, h = c >> 3;
    float s = ss[(size_t)n * 4 + h];
    outp[idx] = fmaxf(acc[idx] / (s + 1e-16f), 0.f);
}

// semantic: accumulate sum over nodes of tanh(o @ kW + kb); blockIdx.y = relation
__global__ void k_semacc(const float* __restrict__ kWl, const float* __restrict__ kbl) {
    int r = blockIdx.y;
    const float* O = (r == 0) ? (const float*)g_oa1 : (const float*)g_oa2;
    __shared__ float sW[HID * HID];
    __shared__ float sb[HID];
    __shared__ float red[HID];
    int tid = threadIdx.x;
    for (int i = tid; i < HID * HID; i += blockDim.x) sW[i] = kWl[i];
    if (tid < HID) { sb[tid] = kbl[tid]; red[tid] = 0.f; }
    __syncthreads();

    float acc[HID];
#pragma unroll
    for (int c = 0; c < HID; c++) acc[c] = 0.f;

    for (int n = blockIdx.x * blockDim.x + tid; n < N_ADDR;
         n += gridDim.x * blockDim.x) {
        const float4* xp = (const float4*)(O + (size_t)n * HID);
        float x[HID];
#pragma unroll
        for (int i = 0; i < 8; i++) {
            float4 v = xp[i];
            x[4 * i] = v.x; x[4 * i + 1] = v.y; x[4 * i + 2] = v.z; x[4 * i + 3] = v.w;
        }
#pragma unroll
        for (int c = 0; c < HID; c++) {
            float dsum = sb[c];
#pragma unroll
            for (int k = 0; k < HID; k++) dsum += x[k] * sW[k * HID + c];
            acc[c] += tanhf(dsum);
        }
    }
#pragma unroll
    for (int c = 0; c < HID; c++) {
        float v = acc[c];
        for (int o = 16; o > 0; o >>= 1) v += __shfl_xor_sync(0xffffffffu, v, o);
        if ((tid & 31) == 0) atomicAdd(&red[c], v);
    }
    __syncthreads();
    if (tid < HID) atomicAdd(&g_sem[r * HID + tid], red[tid]);
}

// softmax over 2 relation scores
__global__ void k_attn(const float* __restrict__ q) {
    int c = threadIdx.x;
    const float inv = 1.0f / (float)N_ADDR;
    float qc = q[c];
    float p0 = g_sem[c] * inv * qc;
    float p1 = g_sem[HID + c] * inv * qc;
    for (int o = 16; o > 0; o >>= 1) {
        p0 += __shfl_xor_sync(0xffffffffu, p0, o);
        p1 += __shfl_xor_sync(0xffffffffu, p1, o);
    }
    if (c == 0) {
        float m = fmaxf(p0, p1);
        float e0 = __expf(p0 - m), e1 = __expf(p1 - m);
        float is = 1.f / (e0 + e1);
        g_attn[0] = e0 * is;
        g_attn[1] = e1 * is;
    }
}

// new addr features = attn-weighted mix (+ wrapper relu, no-op but free)
__global__ void k_mix() {
    int idx = blockIdx.x * blockDim.x + threadIdx.x;
    if (idx >= N_ADDR * HID) return;
    float a0 = g_attn[0], a1 = g_attn[1];
    g_a[idx] = fmaxf(a0 * g_oa1[idx] + a1 * g_oa2[idx], 0.f);
}

// final linear: out[n, 0:2] = a[n,:] @ linW + linb
__global__ void k_lin(const float* __restrict__ linW, const float* __restrict__ linb,
                      float* __restrict__ out) {
    __shared__ float sW[HID * 2];
    __shared__ float sb2[2];
    if (threadIdx.x < HID * 2) sW[threadIdx.x] = linW[threadIdx.x];
    if (threadIdx.x < 2) sb2[threadIdx.x] = linb[threadIdx.x];
    __syncthreads();
    int n = blockIdx.x * blockDim.x + threadIdx.x;
    if (n >= N_ADDR) return;
    const float* ar = g_a + (size_t)n * HID;
    float s0 = sb2[0], s1 = sb2[1];
#pragma unroll
    for (int c = 0; c < HID; c++) {
        float v = ar[c];
        s0 += v * sW[c * 2];
        s1 += v * sW[c * 2 + 1];
    }
    out[(size_t)n * 2] = s0;
    out[(size_t)n * 2 + 1] = s1;
}

// ---------------- host ----------------
extern "C" void kernel_launch(void* const* d_in, const int* in_sizes, int n_in,
                              void* d_out, int out_size) {
    const float* x_addr  = (const float*)d_in[0];
    const float* x_tx    = (const float*)d_in[1];
    const int*   eat_s   = (const int*)d_in[2];
    const int*   eat_d   = (const int*)d_in[3];
    const int*   eta_s   = (const int*)d_in[4];
    const int*   eta_d   = (const int*)d_in[5];
    const int*   eaa_s   = (const int*)d_in[6];
    const int*   eaa_d   = (const int*)d_in[7];
    const float* pW1     = (const float*)d_in[8];
    const float* pb1     = (const float*)d_in[9];
    const float* pW23    = (const float*)d_in[10];
    const float* pb23    = (const float*)d_in[11];
    const float* att_src = (const float*)d_in[12];
    const float* att_dst = (const float*)d_in[13];
    const float* kW      = (const float*)d_in[14];
    const float* kb      = (const float*)d_in[15];
    const float* q       = (const float*)d_in[16];
    const float* linW    = (const float*)d_in[17];
    const float* linb    = (const float*)d_in[18];
    float* out = (float*)d_out;

    const int B = 256;

    for (int l = 0; l < 3; l++) {
        const float *Wa, *ba, *Wt, *bt;
        int F, useExt;
        if (l == 0) {
            Wa = pW1; Wt = pW1 + 64 * HID;
            ba = pb1; bt = pb1 + HID;
            F = 64; useExt = 1;
        } else {
            Wa = pW23 + (size_t)(l - 1) * 2 * HID * HID;
            Wt = Wa + HID * HID;
            ba = pb23 + (size_t)(l - 1) * 2 * HID;
            bt = ba + HID;
            F = HID; useExt = 0;
        }
        k_proj<<<cdiv(N_ADDR * HID, B), B>>>(x_addr, useExt, 1, Wa, ba, N_ADDR, F);
        k_proj<<<cdiv(N_TX * HID, B), B>>>(x_tx, useExt, 0, Wt, bt, N_TX, F);
        k_alpha_addr<<<cdiv(N_ADDR, B), B>>>(att_src + l * 96, att_dst + l * 96);
        k_alpha_tx<<<cdiv(N_TX, B), B>>>(att_src + l * 96, att_dst + l * 96);
        k_clear<<<cdiv(N_TX * HID, B), B>>>();

        k_edge_max<<<cdiv(E_AT, B), B>>>(0, eat_s, eat_d, E_AT);
        k_edge_max<<<cdiv(E_TA, B), B>>>(1, eta_s, eta_d, E_TA);
        k_edge_max<<<cdiv(E_AA, B), B>>>(2, eaa_s, eaa_d, E_AA);
        k_edge_acc<<<cdiv(E_AT, B), B>>>(0, eat_s, eat_d, E_AT);
        k_edge_acc<<<cdiv(E_TA, B), B>>>(1, eta_s, eta_d, E_TA);
        k_edge_acc<<<cdiv(E_AA, B), B>>>(2, eaa_s, eaa_d, E_AA);

        k_finalize<<<cdiv(N_TX * HID, B), B>>>(0);
        k_finalize<<<cdiv(N_ADDR * HID, B), B>>>(1);
        k_finalize<<<cdiv(N_ADDR * HID, B), B>>>(2);

        k_semacc<<<dim3(148, 2), B>>>(kW + (size_t)l * HID * HID, kb + l * HID);
        k_attn<<<1, 32>>>(q + l * HID);
        k_mix<<<cdiv(N_ADDR * HID, B), B>>>();
    }
    k_lin<<<cdiv(N_ADDR, B), B>>>(linW, linb, out);
}

// round 3
// speedup vs baseline: 1.2662x; 1.2662x over previous
#include <cuda_runtime.h>
#include <math.h>

#define N_ADDR 150000
#define N_TX   200000
#define HID    32
#define HEADS  4
#define E_AT   1000000
#define E_TA   1000000
#define E_AA   500000

// ---------------- scratch (device globals; no allocations allowed) ----------------
__device__ __align__(16) float g_ha[(size_t)N_ADDR * HID];   // projected addr features
__device__ __align__(16) float g_ht[(size_t)N_TX * HID];     // projected tx features
__device__ __align__(16) float g_a [(size_t)N_ADDR * HID];   // addr features between layers
__device__ __align__(16) float g_t [(size_t)N_TX * HID];     // tx features between layers

__device__ __align__(16) float g_oa1[(size_t)N_ADDR * HID];  // relation outputs (addr)
__device__ __align__(16) float g_oa2[(size_t)N_ADDR * HID];

__device__ __align__(16) float g_asA0[(size_t)N_ADDR * HEADS]; // alpha_src addr, rel 0 (a->t)
__device__ __align__(16) float g_asA2[(size_t)N_ADDR * HEADS]; // alpha_src addr, rel 2 (a->a)
__device__ __align__(16) float g_adA1[(size_t)N_ADDR * HEADS]; // alpha_dst addr, rel 1 (t->a)
__device__ __align__(16) float g_adA2[(size_t)N_ADDR * HEADS]; // alpha_dst addr, rel 2 (a->a)
__device__ __align__(16) float g_asT [(size_t)N_TX * HEADS];   // alpha_src tx, rel 1
__device__ __align__(16) float g_adT [(size_t)N_TX * HEADS];   // alpha_dst tx, rel 0

// CSR structures (built once per launch; topology shared by all 3 layers)
__device__ int g_cnt[3][N_TX];
__device__ int g_off[3][N_TX + 1];
__device__ int g_cur[3][N_TX];
__device__ int g_bsum[3][128];
__device__ int g_csr0[E_AT];
__device__ int g_csr1[E_TA];
__device__ int g_csr2[E_AA];

__device__ float g_sem[2 * HID];  // semantic accumulators
__device__ float g_attn[2];       // semantic attention weights

// ---------------- helpers ----------------
__device__ __forceinline__ float lrelu(float l) { return l >= 0.f ? l : 0.2f * l; }
static inline int cdiv(int a, int b) { return (a + b - 1) / b; }

// ---------------- CSR build ----------------
__global__ void k_zero_cnt() {
    int i = blockIdx.x * blockDim.x + threadIdx.x;
    if (i < N_TX) g_cnt[0][i] = 0;
    if (i < N_ADDR) { g_cnt[1][i] = 0; g_cnt[2][i] = 0; }
}

__global__ void k_hist(const int* __restrict__ dst, int E, int rel) {
    int e = blockIdx.x * blockDim.x + threadIdx.x;
    if (e < E) atomicAdd(&g_cnt[rel][dst[e]], 1);
}

// block-level exclusive scan: 1024 threads x 4 elements = 4096/block
__global__ void k_scan1(int rel, int N) {
    __shared__ int ws[32];
    const int* cnt = g_cnt[rel];
    int* off = g_off[rel];
    int t = threadIdx.x, lane = t & 31, wid = t >> 5;
    int base = blockIdx.x * 4096 + t * 4;
    int v0 = (base + 0 < N) ? cnt[base + 0] : 0;
    int v1 = (base + 1 < N) ? cnt[base + 1] : 0;
    int v2 = (base + 2 < N) ? cnt[base + 2] : 0;
    int v3 = (base + 3 < N) ? cnt[base + 3] : 0;
    int tsum = v0 + v1 + v2 + v3;
    int x = tsum;
    for (int o = 1; o < 32; o <<= 1) {
        int y = __shfl_up_sync(0xffffffffu, x, o);
        if (lane >= o) x += y;
    }
    if (lane == 31) ws[wid] = x;
    __syncthreads();
    if (wid == 0) {
        int w = ws[lane];
        for (int o = 1; o < 32; o <<= 1) {
            int y = __shfl_up_sync(0xffffffffu, w, o);
            if (lane >= o) w += y;
        }
        ws[lane] = w;  // inclusive scan of warp totals
    }
    __syncthreads();
    int excl = x - tsum + (wid > 0 ? ws[wid - 1] : 0);
    if (base + 0 < N) off[base + 0] = excl;
    if (base + 1 < N) off[base + 1] = excl + v0;
    if (base + 2 < N) off[base + 2] = excl + v0 + v1;
    if (base + 3 < N) off[base + 3] = excl + v0 + v1 + v2;
    if (t == 1023) g_bsum[rel][blockIdx.x] = excl + tsum;
}

__global__ void k_scan2(int rel, int nb) {
    __shared__ int sh[128];
    int t = threadIdx.x;
    int orig = (t < nb) ? g_bsum[rel][t] : 0;
    sh[t] = orig;
    __syncthreads();
    for (int o = 1; o < 128; o <<= 1) {
        int v = (t >= o) ? sh[t - o] : 0;
        __syncthreads();
        sh[t] += v;
        __syncthreads();
    }
    if (t < nb) g_bsum[rel][t] = sh[t] - orig;  // exclusive
}

__global__ void k_scan3(int rel, int N) {
    int i = blockIdx.x * blockDim.x + threadIdx.x;
    if (i >= N) return;
    int o = g_off[rel][i] + g_bsum[rel][i >> 12];
    g_off[rel][i] = o;
    g_cur[rel][i] = o;
    if (i == N - 1) g_off[rel][N] = o + g_cnt[rel][i];
}

// NOTE: csr target selected IN DEVICE CODE — passing __device__ symbols as
// kernel args from host yields the wrong address (R2 bug).
__global__ void k_scatter(const int* __restrict__ src, const int* __restrict__ dst,
                          int E, int rel) {
    int* csr = (rel == 0) ? g_csr0 : (rel == 1) ? g_csr1 : g_csr2;
    int e = blockIdx.x * blockDim.x + threadIdx.x;
    if (e < E) {
        int p = atomicAdd(&g_cur[rel][dst[e]], 1);
        csr[p] = src[e];
    }
}

// ---------------- per-layer kernels ----------------

// out[n,c] = x[n,:] @ W[:,c] + b[c]
__global__ void k_proj(const float* __restrict__ xext, int useExt, int isAddr,
                       const float* __restrict__ W, const float* __restrict__ b,
                       int N, int F) {
    __shared__ float sW[64 * HID];
    __shared__ float sb[HID];
    for (int i = threadIdx.x; i < F * HID; i += blockDim.x) sW[i] = W[i];
    if (threadIdx.x < HID) sb[threadIdx.x] = b[threadIdx.x];
    __syncthreads();

    const float* x = useExt ? xext : (isAddr ? (const float*)g_a : (const float*)g_t);
    float* outp = isAddr ? g_ha : g_ht;

    int idx = blockIdx.x * blockDim.x + threadIdx.x;
    int n = idx >> 5, c = idx & 31;
    if (n >= N) return;
    const float* xr = x + (size_t)n * F;
    float acc = sb[c];
    for (int k = 0; k < F; k++) acc += xr[k] * sW[k * HID + c];
    outp[(size_t)n * HID + c] = acc;
}

__global__ void k_alpha_addr(const float* __restrict__ as_l, const float* __restrict__ ad_l) {
    __shared__ float v0[32], v2[32], d1[32], d2[32];
    int tid = threadIdx.x;
    if (tid < 32) {
        v0[tid] = as_l[tid];
        v2[tid] = as_l[64 + tid];
        d1[tid] = ad_l[32 + tid];
        d2[tid] = ad_l[64 + tid];
    }
    __syncthreads();
    int n = blockIdx.x * blockDim.x + tid;
    if (n >= N_ADDR) return;
    const float4* hp = (const float4*)(g_ha + (size_t)n * HID);
    float x[32];
#pragma unroll
    for (int i = 0; i < 8; i++) {
        float4 v = hp[i];
        x[4 * i] = v.x; x[4 * i + 1] = v.y; x[4 * i + 2] = v.z; x[4 * i + 3] = v.w;
    }
    float r0[4], r2[4], s1[4], s2[4];
#pragma unroll
    for (int h = 0; h < 4; h++) {
        float a0 = 0.f, a2 = 0.f, b1 = 0.f, b2 = 0.f;
#pragma unroll
        for (int d = 0; d < 8; d++) {
            int i = h * 8 + d;
            a0 += x[i] * v0[i]; a2 += x[i] * v2[i];
            b1 += x[i] * d1[i]; b2 += x[i] * d2[i];
        }
        r0[h] = a0; r2[h] = a2; s1[h] = b1; s2[h] = b2;
    }
    *(float4*)(g_asA0 + (size_t)n * 4) = make_float4(r0[0], r0[1], r0[2], r0[3]);
    *(float4*)(g_asA2 + (size_t)n * 4) = make_float4(r2[0], r2[1], r2[2], r2[3]);
    *(float4*)(g_adA1 + (size_t)n * 4) = make_float4(s1[0], s1[1], s1[2], s1[3]);
    *(float4*)(g_adA2 + (size_t)n * 4) = make_float4(s2[0], s2[1], s2[2], s2[3]);
}

__global__ void k_alpha_tx(const float* __restrict__ as_l, const float* __restrict__ ad_l) {
    __shared__ float v1[32], d0[32];
    int tid = threadIdx.x;
    if (tid < 32) {
        v1[tid] = as_l[32 + tid];
        d0[tid] = ad_l[tid];
    }
    __syncthreads();
    int n = blockIdx.x * blockDim.x + tid;
    if (n >= N_TX) return;
    const float4* hp = (const float4*)(g_ht + (size_t)n * HID);
    float x[32];
#pragma unroll
    for (int i = 0; i < 8; i++) {
        float4 v = hp[i];
        x[4 * i] = v.x; x[4 * i + 1] = v.y; x[4 * i + 2] = v.z; x[4 * i + 3] = v.w;
    }
    float rs[4], rd[4];
#pragma unroll
    for (int h = 0; h < 4; h++) {
        float a = 0.f, b = 0.f;
#pragma unroll
        for (int d = 0; d < 8; d++) {
            int i = h * 8 + d;
            a += x[i] * v1[i]; b += x[i] * d0[i];
        }
        rs[h] = a; rd[h] = b;
    }
    *(float4*)(g_asT + (size_t)n * 4) = make_float4(rs[0], rs[1], rs[2], rs[3]);
    *(float4*)(g_adT + (size_t)n * 4) = make_float4(rd[0], rd[1], rd[2], rd[3]);
}

// gather-based relation aggregation: one warp per dst node, lane = channel.
// rel 0: addr->tx (out = new tx features), rel 1: tx->addr, rel 2: addr->addr
__global__ void k_agg(int rel) {
    const int* off; const int* csr;
    const float* as_; const float* ad_; const float* hs; float* outp; int N;
    if (rel == 0)      { off = g_off[0]; csr = g_csr0; as_ = g_asA0; ad_ = g_adT;  hs = g_ha; outp = g_t;   N = N_TX; }
    else if (rel == 1) { off = g_off[1]; csr = g_csr1; as_ = g_asT;  ad_ = g_adA1; hs = g_ht; outp = g_oa1; N = N_ADDR; }
    else               { off = g_off[2]; csr = g_csr2; as_ = g_asA2; ad_ = g_adA2; hs = g_ha; outp = g_oa2; N = N_ADDR; }

    int warp = (blockIdx.x * blockDim.x + threadIdx.x) >> 5;
    int lane = threadIdx.x & 31;
    if (warp >= N) return;
    int start = off[warp], end = off[warp + 1];
    if (start == end) { outp[(size_t)warp * HID + lane] = 0.f; return; }

    float4 adv = *(const float4*)(ad_ + (size_t)warp * 4);
    const float NEG = __int_as_float(0xff800000);

    // pass 1: per-head max of leaky-relu logits over neighbors
    float4 m = make_float4(NEG, NEG, NEG, NEG);
    for (int base = start; base < end; base += 32) {
        int e = base + lane;
        if (e < end) {
            int s = csr[e];
            float4 av = *(const float4*)(as_ + (size_t)s * 4);
            float4 L = make_float4(lrelu(av.x + adv.x), lrelu(av.y + adv.y),
                                   lrelu(av.z + adv.z), lrelu(av.w + adv.w));
            m.x = fmaxf(m.x, L.x); m.y = fmaxf(m.y, L.y);
            m.z = fmaxf(m.z, L.z); m.w = fmaxf(m.w, L.w);
        }
    }
#pragma unroll
    for (int o = 16; o > 0; o >>= 1) {
        m.x = fmaxf(m.x, __shfl_xor_sync(0xffffffffu, m.x, o));
        m.y = fmaxf(m.y, __shfl_xor_sync(0xffffffffu, m.y, o));
        m.z = fmaxf(m.z, __shfl_xor_sync(0xffffffffu, m.z, o));
        m.w = fmaxf(m.w, __shfl_xor_sync(0xffffffffu, m.w, o));
    }

    int h = lane >> 3;
    // pass 2: exp-weighted accumulation
    float ssum = 0.f, acc = 0.f;
    for (int base = start; base < end; base += 32) {
        int e = base + lane;
        int cnt = min(32, end - base);
        int s = 0;
        float4 w4 = make_float4(0.f, 0.f, 0.f, 0.f);
        if (e < end) {
            s = csr[e];
            float4 av = *(const float4*)(as_ + (size_t)s * 4);
            w4.x = __expf(lrelu(av.x + adv.x) - m.x);
            w4.y = __expf(lrelu(av.y + adv.y) - m.y);
            w4.z = __expf(lrelu(av.z + adv.z) - m.z);
            w4.w = __expf(lrelu(av.w + adv.w) - m.w);
        }
        for (int j = 0; j < cnt; j++) {
            int sj = __shfl_sync(0xffffffffu, s, j);
            float w0 = __shfl_sync(0xffffffffu, w4.x, j);
            float w1 = __shfl_sync(0xffffffffu, w4.y, j);
            float w2 = __shfl_sync(0xffffffffu, w4.z, j);
            float w3 = __shfl_sync(0xffffffffu, w4.w, j);
            float w = (h == 0) ? w0 : (h == 1) ? w1 : (h == 2) ? w2 : w3;
            ssum += w;
            acc += w * hs[(size_t)sj * HID + lane];
        }
    }
    outp[(size_t)warp * HID + lane] = fmaxf(acc / (ssum + 1e-16f), 0.f);
}

__global__ void k_zero_sem() {
    int t = threadIdx.x;
    if (t < 2 * HID) g_sem[t] = 0.f;
}

// semantic: accumulate sum over nodes of tanh(o @ kW + kb); blockIdx.y = relation
__global__ void k_semacc(const float* __restrict__ kWl, const float* __restrict__ kbl) {
    int r = blockIdx.y;
    const float* O = (r == 0) ? (const float*)g_oa1 : (const float*)g_oa2;
    __shared__ float sW[HID * HID];
    __shared__ float sb[HID];
    __shared__ float red[HID];
    int tid = threadIdx.x;
    for (int i = tid; i < HID * HID; i += blockDim.x) sW[i] = kWl[i];
    if (tid < HID) { sb[tid] = kbl[tid]; red[tid] = 0.f; }
    __syncthreads();

    float acc[HID];
#pragma unroll
    for (int c = 0; c < HID; c++) acc[c] = 0.f;

    for (int n = blockIdx.x * blockDim.x + tid; n < N_ADDR;
         n += gridDim.x * blockDim.x) {
        const float4* xp = (const float4*)(O + (size_t)n * HID);
        float x[HID];
#pragma unroll
        for (int i = 0; i < 8; i++) {
            float4 v = xp[i];
            x[4 * i] = v.x; x[4 * i + 1] = v.y; x[4 * i + 2] = v.z; x[4 * i + 3] = v.w;
        }
#pragma unroll
        for (int c = 0; c < HID; c++) {
            float dsum = sb[c];
#pragma unroll
            for (int k = 0; k < HID; k++) dsum += x[k] * sW[k * HID + c];
            acc[c] += tanhf(dsum);
        }
    }
#pragma unroll
    for (int c = 0; c < HID; c++) {
        float v = acc[c];
        for (int o = 16; o > 0; o >>= 1) v += __shfl_xor_sync(0xffffffffu, v, o);
        if ((tid & 31) == 0) atomicAdd(&red[c], v);
    }
    __syncthreads();
    if (tid < HID) atomicAdd(&g_sem[r * HID + tid], red[tid]);
}

__global__ void k_attn(const float* __restrict__ q) {
    int c = threadIdx.x;
    const float inv = 1.0f / (float)N_ADDR;
    float qc = q[c];
    float p0 = g_sem[c] * inv * qc;
    float p1 = g_sem[HID + c] * inv * qc;
    for (int o = 16; o > 0; o >>= 1) {
        p0 += __shfl_xor_sync(0xffffffffu, p0, o);
        p1 += __shfl_xor_sync(0xffffffffu, p1, o);
    }
    if (c == 0) {
        float m = fmaxf(p0, p1);
        float e0 = __expf(p0 - m), e1 = __expf(p1 - m);
        float is = 1.f / (e0 + e1);
        g_attn[0] = e0 * is;
        g_attn[1] = e1 * is;
    }
}

__global__ void k_mix() {
    int idx = blockIdx.x * blockDim.x + threadIdx.x;
    if (idx >= N_ADDR * HID) return;
    float a0 = g_attn[0], a1 = g_attn[1];
    g_a[idx] = fmaxf(a0 * g_oa1[idx] + a1 * g_oa2[idx], 0.f);
}

__global__ void k_lin(const float* __restrict__ linW, const float* __restrict__ linb,
                      float* __restrict__ out) {
    __shared__ float sW[HID * 2];
    __shared__ float sb2[2];
    if (threadIdx.x < HID * 2) sW[threadIdx.x] = linW[threadIdx.x];
    if (threadIdx.x < 2) sb2[threadIdx.x] = linb[threadIdx.x];
    __syncthreads();
    int n = blockIdx.x * blockDim.x + threadIdx.x;
    if (n >= N_ADDR) return;
    const float* ar = g_a + (size_t)n * HID;
    float s0 = sb2[0], s1 = sb2[1];
#pragma unroll
    for (int c = 0; c < HID; c++) {
        float v = ar[c];
        s0 += v * sW[c * 2];
        s1 += v * sW[c * 2 + 1];
    }
    out[(size_t)n * 2] = s0;
    out[(size_t)n * 2 + 1] = s1;
}

// ---------------- host ----------------
extern "C" void kernel_launch(void* const* d_in, const int* in_sizes, int n_in,
                              void* d_out, int out_size) {
    const float* x_addr  = (const float*)d_in[0];
    const float* x_tx    = (const float*)d_in[1];
    const int*   eat_s   = (const int*)d_in[2];
    const int*   eat_d   = (const int*)d_in[3];
    const int*   eta_s   = (const int*)d_in[4];
    const int*   eta_d   = (const int*)d_in[5];
    const int*   eaa_s   = (const int*)d_in[6];
    const int*   eaa_d   = (const int*)d_in[7];
    const float* pW1     = (const float*)d_in[8];
    const float* pb1     = (const float*)d_in[9];
    const float* pW23    = (const float*)d_in[10];
    const float* pb23    = (const float*)d_in[11];
    const float* att_src = (const float*)d_in[12];
    const float* att_dst = (const float*)d_in[13];
    const float* kW      = (const float*)d_in[14];
    const float* kb      = (const float*)d_in[15];
    const float* q       = (const float*)d_in[16];
    const float* linW    = (const float*)d_in[17];
    const float* linb    = (const float*)d_in[18];
    float* out = (float*)d_out;

    const int B = 256;
    int csrN[3] = { N_TX, N_ADDR, N_ADDR };
    const int* dsts[3] = { eat_d, eta_d, eaa_d };
    int Es[3] = { E_AT, E_TA, E_AA };

    // ---- build CSR once (topology shared across layers) ----
    k_zero_cnt<<<cdiv(N_TX, B), B>>>();
    for (int r = 0; r < 3; r++)
        k_hist<<<cdiv(Es[r], B), B>>>(dsts[r], Es[r], r);
    for (int r = 0; r < 3; r++) {
        int nb = cdiv(csrN[r], 4096);
        k_scan1<<<nb, 1024>>>(r, csrN[r]);
        k_scan2<<<1, 128>>>(r, nb);
        k_scan3<<<cdiv(csrN[r], B), B>>>(r, csrN[r]);
    }
    k_scatter<<<cdiv(E_AT, B), B>>>(eat_s, eat_d, E_AT, 0);
    k_scatter<<<cdiv(E_TA, B), B>>>(eta_s, eta_d, E_TA, 1);
    k_scatter<<<cdiv(E_AA, B), B>>>(eaa_s, eaa_d, E_AA, 2);

    // ---- layers ----
    for (int l = 0; l < 3; l++) {
        const float *Wa, *ba, *Wt, *bt;
        int F, useExt;
        if (l == 0) {
            Wa = pW1; Wt = pW1 + 64 * HID;
            ba = pb1; bt = pb1 + HID;
            F = 64; useExt = 1;
        } else {
            Wa = pW23 + (size_t)(l - 1) * 2 * HID * HID;
            Wt = Wa + HID * HID;
            ba = pb23 + (size_t)(l - 1) * 2 * HID;
            bt = ba + HID;
            F = HID; useExt = 0;
        }
        k_proj<<<cdiv(N_ADDR * HID, B), B>>>(x_addr, useExt, 1, Wa, ba, N_ADDR, F);
        k_proj<<<cdiv(N_TX * HID, B), B>>>(x_tx, useExt, 0, Wt, bt, N_TX, F);
        k_alpha_addr<<<cdiv(N_ADDR, B), B>>>(att_src + l * 96, att_dst + l * 96);
        k_alpha_tx<<<cdiv(N_TX, B), B>>>(att_src + l * 96, att_dst + l * 96);

        k_agg<<<cdiv(N_TX, 8), B>>>(0);     // addr->tx, writes new g_t
        k_agg<<<cdiv(N_ADDR, 8), B>>>(1);   // tx->addr  -> g_oa1
        k_agg<<<cdiv(N_ADDR, 8), B>>>(2);   // addr->addr-> g_oa2

        k_zero_sem<<<1, 64>>>();
        k_semacc<<<dim3(148, 2), B>>>(kW + (size_t)l * HID * HID, kb + l * HID);
        k_attn<<<1, 32>>>(q + l * HID);
        k_mix<<<cdiv(N_ADDR * HID, B), B>>>();
    }
    k_lin<<<cdiv(N_ADDR, B), B>>>(linW, linb, out);
}

// round 4
// speedup vs baseline: 1.5464x; 1.2212x over previous
#include <cuda_runtime.h>
#include <math.h>

#define N_ADDR 150000
#define N_TX   200000
#define HID    32
#define HEADS  4
#define E_AT   1000000
#define E_TA   1000000
#define E_AA   500000

// ---------------- scratch (device globals; no allocations allowed) ----------------
__device__ __align__(16) float g_ha[(size_t)N_ADDR * HID];   // projected addr features
__device__ __align__(16) float g_ht[(size_t)N_TX * HID];     // projected tx features
__device__ __align__(16) float g_a [(size_t)N_ADDR * HID];   // addr features between layers
__device__ __align__(16) float g_t [(size_t)N_TX * HID];     // tx features between layers

__device__ __align__(16) float g_oa1[(size_t)N_ADDR * HID];  // relation outputs (addr)
__device__ __align__(16) float g_oa2[(size_t)N_ADDR * HID];

__device__ __align__(16) float g_asA0[(size_t)N_ADDR * HEADS]; // alpha_src addr, rel 0 (a->t)
__device__ __align__(16) float g_asA2[(size_t)N_ADDR * HEADS]; // alpha_src addr, rel 2 (a->a)
__device__ __align__(16) float g_adA1[(size_t)N_ADDR * HEADS]; // alpha_dst addr, rel 1 (t->a)
__device__ __align__(16) float g_adA2[(size_t)N_ADDR * HEADS]; // alpha_dst addr, rel 2 (a->a)
__device__ __align__(16) float g_asT [(size_t)N_TX * HEADS];   // alpha_src tx, rel 1
__device__ __align__(16) float g_adT [(size_t)N_TX * HEADS];   // alpha_dst tx, rel 0

// CSR structures (built once per launch; topology shared by all 3 layers)
__device__ int g_cnt[3][N_TX];
__device__ int g_off[3][N_TX + 1];
__device__ int g_cur[3][N_TX];
__device__ int g_bsum[3][128];
__device__ int g_csr0[E_AT];
__device__ int g_csr1[E_TA];
__device__ int g_csr2[E_AA];

__device__ unsigned g_gmax[3 * HEADS]; // encoded global per-head max of alpha_src
__device__ float g_sem[2 * HID];       // semantic accumulators
__device__ float g_attn[2];            // semantic attention weights

// ---------------- helpers ----------------
__device__ __forceinline__ unsigned fenc(float x) {
    unsigned b = __float_as_uint(x);
    return (b & 0x80000000u) ? ~b : (b | 0x80000000u);
}
__device__ __forceinline__ float fdec(unsigned u) {
    return (u & 0x80000000u) ? __uint_as_float(u & 0x7FFFFFFFu)
                             : __uint_as_float(~u);
}
__device__ __forceinline__ float lrelu(float l) { return l >= 0.f ? l : 0.2f * l; }
static inline int cdiv(int a, int b) { return (a + b - 1) / b; }

// ---------------- CSR build ----------------
__global__ void k_zero_cnt() {
    int i = blockIdx.x * blockDim.x + threadIdx.x;
    if (i < N_TX) g_cnt[0][i] = 0;
    if (i < N_ADDR) { g_cnt[1][i] = 0; g_cnt[2][i] = 0; }
}

__global__ void k_hist(const int* __restrict__ dst, int E, int rel) {
    int e = blockIdx.x * blockDim.x + threadIdx.x;
    if (e < E) atomicAdd(&g_cnt[rel][dst[e]], 1);
}

__global__ void k_scan1(int rel, int N) {
    __shared__ int ws[32];
    const int* cnt = g_cnt[rel];
    int* off = g_off[rel];
    int t = threadIdx.x, lane = t & 31, wid = t >> 5;
    int base = blockIdx.x * 4096 + t * 4;
    int v0 = (base + 0 < N) ? cnt[base + 0] : 0;
    int v1 = (base + 1 < N) ? cnt[base + 1] : 0;
    int v2 = (base + 2 < N) ? cnt[base + 2] : 0;
    int v3 = (base + 3 < N) ? cnt[base + 3] : 0;
    int tsum = v0 + v1 + v2 + v3;
    int x = tsum;
    for (int o = 1; o < 32; o <<= 1) {
        int y = __shfl_up_sync(0xffffffffu, x, o);
        if (lane >= o) x += y;
    }
    if (lane == 31) ws[wid] = x;
    __syncthreads();
    if (wid == 0) {
        int w = ws[lane];
        for (int o = 1; o < 32; o <<= 1) {
            int y = __shfl_up_sync(0xffffffffu, w, o);
            if (lane >= o) w += y;
        }
        ws[lane] = w;
    }
    __syncthreads();
    int excl = x - tsum + (wid > 0 ? ws[wid - 1] : 0);
    if (base + 0 < N) off[base + 0] = excl;
    if (base + 1 < N) off[base + 1] = excl + v0;
    if (base + 2 < N) off[base + 2] = excl + v0 + v1;
    if (base + 3 < N) off[base + 3] = excl + v0 + v1 + v2;
    if (t == 1023) g_bsum[rel][blockIdx.x] = excl + tsum;
}

__global__ void k_scan2(int rel, int nb) {
    __shared__ int sh[128];
    int t = threadIdx.x;
    int orig = (t < nb) ? g_bsum[rel][t] : 0;
    sh[t] = orig;
    __syncthreads();
    for (int o = 1; o < 128; o <<= 1) {
        int v = (t >= o) ? sh[t - o] : 0;
        __syncthreads();
        sh[t] += v;
        __syncthreads();
    }
    if (t < nb) g_bsum[rel][t] = sh[t] - orig;
}

__global__ void k_scan3(int rel, int N) {
    int i = blockIdx.x * blockDim.x + threadIdx.x;
    if (i >= N) return;
    int o = g_off[rel][i] + g_bsum[rel][i >> 12];
    g_off[rel][i] = o;
    g_cur[rel][i] = o;
    if (i == N - 1) g_off[rel][N] = o + g_cnt[rel][i];
}

// csr target selected IN DEVICE CODE (host-side __device__ symbol = wrong addr)
__global__ void k_scatter(const int* __restrict__ src, const int* __restrict__ dst,
                          int E, int rel) {
    int* csr = (rel == 0) ? g_csr0 : (rel == 1) ? g_csr1 : g_csr2;
    int e = blockIdx.x * blockDim.x + threadIdx.x;
    if (e < E) {
        int p = atomicAdd(&g_cur[rel][dst[e]], 1);
        csr[p] = src[e];
    }
}

// ---------------- per-layer kernels ----------------

// fused projection + node-level attention dot products.
// one warp per node, lane = channel c; alpha dot products reduced within 8-lane
// head groups via shuffles.
__global__ void k_proj_fused(const float* __restrict__ xext, int useExt, int isAddr,
                             const float* __restrict__ W, const float* __restrict__ b,
                             const float* __restrict__ as_l, const float* __restrict__ ad_l,
                             int N, int F) {
    __shared__ float sW[64 * HID];
    __shared__ float sb[HID];
    __shared__ float sv[4][HID];
    int tid = threadIdx.x;
    for (int i = tid; i < F * HID; i += blockDim.x) sW[i] = W[i];
    if (tid < HID) {
        sb[tid] = b[tid];
        if (isAddr) {
            sv[0][tid] = as_l[tid];        // rel0 src (a->t)
            sv[1][tid] = as_l[64 + tid];   // rel2 src (a->a)
            sv[2][tid] = ad_l[32 + tid];   // rel1 dst (t->a)
            sv[3][tid] = ad_l[64 + tid];   // rel2 dst (a->a)
        } else {
            sv[0][tid] = as_l[32 + tid];   // rel1 src (t->a)
            sv[1][tid] = ad_l[tid];        // rel0 dst (a->t)
        }
    }
    __syncthreads();

    int idx = blockIdx.x * blockDim.x + tid;
    int n = idx >> 5, c = idx & 31;
    if (n >= N) return;

    const float* x = useExt ? xext : (isAddr ? (const float*)g_a : (const float*)g_t);
    const float* xr = x + (size_t)n * F;
    float acc = sb[c];
    for (int k = 0; k < F; k++) acc += xr[k] * sW[k * HID + c];
    (isAddr ? g_ha : g_ht)[(size_t)n * HID + c] = acc;

    int h = c >> 3;
    float p0 = acc * sv[0][c];
    float p1 = acc * sv[1][c];
    float p2 = 0.f, p3 = 0.f;
    if (isAddr) { p2 = acc * sv[2][c]; p3 = acc * sv[3][c]; }
#pragma unroll
    for (int o = 4; o > 0; o >>= 1) {
        p0 += __shfl_xor_sync(0xffffffffu, p0, o);
        p1 += __shfl_xor_sync(0xffffffffu, p1, o);
        p2 += __shfl_xor_sync(0xffffffffu, p2, o);
        p3 += __shfl_xor_sync(0xffffffffu, p3, o);
    }
    if ((c & 7) == 0) {
        if (isAddr) {
            g_asA0[(size_t)n * 4 + h] = p0;
            g_asA2[(size_t)n * 4 + h] = p1;
            g_adA1[(size_t)n * 4 + h] = p2;
            g_adA2[(size_t)n * 4 + h] = p3;
        } else {
            g_asT[(size_t)n * 4 + h] = p0;
            g_adT[(size_t)n * 4 + h] = p1;
        }
    }
}

// zero per-layer reduction state
__global__ void k_layer_init() {
    int t = threadIdx.x;
    if (t < 2 * HID) g_sem[t] = 0.f;
    if (t < 3 * HEADS) g_gmax[t] = 0u;  // 0 < fenc(x) for all finite x
}

// global per-head max of alpha_src for each relation (softmax upper bound)
__global__ void k_amax() {
    int r = blockIdx.y;
    const float4* A; int N;
    if (r == 0)      { A = (const float4*)g_asA0; N = N_ADDR; }
    else if (r == 1) { A = (const float4*)g_asT;  N = N_TX; }
    else             { A = (const float4*)g_asA2; N = N_ADDR; }
    const float NEG = __int_as_float(0xff800000);
    float4 m = make_float4(NEG, NEG, NEG, NEG);
    for (int i = blockIdx.x * blockDim.x + threadIdx.x; i < N;
         i += gridDim.x * blockDim.x) {
        float4 v = A[i];
        m.x = fmaxf(m.x, v.x); m.y = fmaxf(m.y, v.y);
        m.z = fmaxf(m.z, v.z); m.w = fmaxf(m.w, v.w);
    }
#pragma unroll
    for (int o = 16; o > 0; o >>= 1) {
        m.x = fmaxf(m.x, __shfl_xor_sync(0xffffffffu, m.x, o));
        m.y = fmaxf(m.y, __shfl_xor_sync(0xffffffffu, m.y, o));
        m.z = fmaxf(m.z, __shfl_xor_sync(0xffffffffu, m.z, o));
        m.w = fmaxf(m.w, __shfl_xor_sync(0xffffffffu, m.w, o));
    }
    __shared__ float4 sm[8];
    int lane = threadIdx.x & 31, wid = threadIdx.x >> 5;
    if (lane == 0) sm[wid] = m;
    __syncthreads();
    if (threadIdx.x < 8) {
        float4 v = sm[threadIdx.x];
#pragma unroll
        for (int o = 4; o > 0; o >>= 1) {
            v.x = fmaxf(v.x, __shfl_xor_sync(0xffu, v.x, o));
            v.y = fmaxf(v.y, __shfl_xor_sync(0xffu, v.y, o));
            v.z = fmaxf(v.z, __shfl_xor_sync(0xffu, v.z, o));
            v.w = fmaxf(v.w, __shfl_xor_sync(0xffu, v.w, o));
        }
        if (threadIdx.x == 0) {
            atomicMax(&g_gmax[r * 4 + 0], fenc(v.x));
            atomicMax(&g_gmax[r * 4 + 1], fenc(v.y));
            atomicMax(&g_gmax[r * 4 + 2], fenc(v.z));
            atomicMax(&g_gmax[r * 4 + 3], fenc(v.w));
        }
    }
}

// fused gather aggregation for all 3 relations. one warp per dst node;
// 4 edges processed in parallel per iteration (8 lanes per edge, lane = float4
// channel block). single pass: softmax uses the global alpha_src max bound.
__global__ void k_agg_all() {
    int gw = blockIdx.x * (blockDim.x >> 5) + (threadIdx.x >> 5);
    int lane = threadIdx.x & 31;
    int rel, node;
    if (gw < N_TX) { rel = 0; node = gw; }
    else if (gw < N_TX + N_ADDR) { rel = 1; node = gw - N_TX; }
    else if (gw < N_TX + 2 * N_ADDR) { rel = 2; node = gw - N_TX - N_ADDR; }
    else return;

    const int* off; const int* csr; const float* as_; const float* ad_;
    const float* hs; float* outp;
    if (rel == 0)      { off = g_off[0]; csr = g_csr0; as_ = g_asA0; ad_ = g_adT;  hs = g_ha; outp = g_t; }
    else if (rel == 1) { off = g_off[1]; csr = g_csr1; as_ = g_asT;  ad_ = g_adA1; hs = g_ht; outp = g_oa1; }
    else               { off = g_off[2]; csr = g_csr2; as_ = g_asA2; ad_ = g_adA2; hs = g_ha; outp = g_oa2; }

    int start = off[node], end = off[node + 1];
    int c4 = lane & 7, g = lane >> 3, h = c4 >> 1;
    float* orow = outp + (size_t)node * HID;
    if (start == end) {
        if (lane < 8) ((float4*)orow)[c4] = make_float4(0.f, 0.f, 0.f, 0.f);
        return;
    }
    float adv = ad_[(size_t)node * 4 + h];
    float m = lrelu(fdec(g_gmax[rel * 4 + h]) + adv);  // >= all edge logits (lrelu monotone)

    float4 acc = make_float4(0.f, 0.f, 0.f, 0.f);
    float ssum = 0.f;
    for (int base = start; base < end; base += 4) {
        int e = base + g;
        if (e < end) {
            int s = csr[e];
            float a = as_[(size_t)s * 4 + h];
            float w = __expf(lrelu(a + adv) - m);
            float4 f = *(const float4*)(hs + (size_t)s * HID + c4 * 4);
            acc.x += w * f.x; acc.y += w * f.y;
            acc.z += w * f.z; acc.w += w * f.w;
            ssum += w;
        }
    }
#pragma unroll
    for (int o = 8; o <= 16; o <<= 1) {
        acc.x += __shfl_xor_sync(0xffffffffu, acc.x, o);
        acc.y += __shfl_xor_sync(0xffffffffu, acc.y, o);
        acc.z += __shfl_xor_sync(0xffffffffu, acc.z, o);
        acc.w += __shfl_xor_sync(0xffffffffu, acc.w, o);
        ssum  += __shfl_xor_sync(0xffffffffu, ssum, o);
    }
    if (lane < 8) {
        float inv = 1.f / (ssum + 1e-16f);
        ((float4*)orow)[c4] = make_float4(fmaxf(acc.x * inv, 0.f),
                                          fmaxf(acc.y * inv, 0.f),
                                          fmaxf(acc.z * inv, 0.f),
                                          fmaxf(acc.w * inv, 0.f));
    }
}

// semantic: accumulate sum over nodes of tanh(o @ kW + kb); blockIdx.y = relation
__global__ void k_semacc(const float* __restrict__ kWl, const float* __restrict__ kbl) {
    int r = blockIdx.y;
    const float* O = (r == 0) ? (const float*)g_oa1 : (const float*)g_oa2;
    __shared__ float sW[HID * HID];
    __shared__ float sb[HID];
    __shared__ float red[HID];
    int tid = threadIdx.x;
    for (int i = tid; i < HID * HID; i += blockDim.x) sW[i] = kWl[i];
    if (tid < HID) { sb[tid] = kbl[tid]; red[tid] = 0.f; }
    __syncthreads();

    float acc[HID];
#pragma unroll
    for (int c = 0; c < HID; c++) acc[c] = 0.f;

    for (int n = blockIdx.x * blockDim.x + tid; n < N_ADDR;
         n += gridDim.x * blockDim.x) {
        const float4* xp = (const float4*)(O + (size_t)n * HID);
        float x[HID];
#pragma unroll
        for (int i = 0; i < 8; i++) {
            float4 v = xp[i];
            x[4 * i] = v.x; x[4 * i + 1] = v.y; x[4 * i + 2] = v.z; x[4 * i + 3] = v.w;
        }
#pragma unroll
        for (int c = 0; c < HID; c++) {
            float dsum = sb[c];
#pragma unroll
            for (int k = 0; k < HID; k++) dsum += x[k] * sW[k * HID + c];
            acc[c] += tanhf(dsum);
        }
    }
#pragma unroll
    for (int c = 0; c < HID; c++) {
        float v = acc[c];
        for (int o = 16; o > 0; o >>= 1) v += __shfl_xor_sync(0xffffffffu, v, o);
        if ((tid & 31) == 0) atomicAdd(&red[c], v);
    }
    __syncthreads();
    if (tid < HID) atomicAdd(&g_sem[r * HID + tid], red[tid]);
}

__global__ void k_attn(const float* __restrict__ q) {
    int c = threadIdx.x;
    const float inv = 1.0f / (float)N_ADDR;
    float qc = q[c];
    float p0 = g_sem[c] * inv * qc;
    float p1 = g_sem[HID + c] * inv * qc;
    for (int o = 16; o > 0; o >>= 1) {
        p0 += __shfl_xor_sync(0xffffffffu, p0, o);
        p1 += __shfl_xor_sync(0xffffffffu, p1, o);
    }
    if (c == 0) {
        float m = fmaxf(p0, p1);
        float e0 = __expf(p0 - m), e1 = __expf(p1 - m);
        float is = 1.f / (e0 + e1);
        g_attn[0] = e0 * is;
        g_attn[1] = e1 * is;
    }
}

__global__ void k_mix() {
    int idx = blockIdx.x * blockDim.x + threadIdx.x;
    if (idx >= N_ADDR * HID) return;
    float a0 = g_attn[0], a1 = g_attn[1];
    g_a[idx] = fmaxf(a0 * g_oa1[idx] + a1 * g_oa2[idx], 0.f);
}

__global__ void k_lin(const float* __restrict__ linW, const float* __restrict__ linb,
                      float* __restrict__ out) {
    __shared__ float sW[HID * 2];
    __shared__ float sb2[2];
    if (threadIdx.x < HID * 2) sW[threadIdx.x] = linW[threadIdx.x];
    if (threadIdx.x < 2) sb2[threadIdx.x] = linb[threadIdx.x];
    __syncthreads();
    int n = blockIdx.x * blockDim.x + threadIdx.x;
    if (n >= N_ADDR) return;
    const float* ar = g_a + (size_t)n * HID;
    float s0 = sb2[0], s1 = sb2[1];
#pragma unroll
    for (int c = 0; c < HID; c++) {
        float v = ar[c];
        s0 += v * sW[c * 2];
        s1 += v * sW[c * 2 + 1];
    }
    out[(size_t)n * 2] = s0;
    out[(size_t)n * 2 + 1] = s1;
}

// ---------------- host ----------------
extern "C" void kernel_launch(void* const* d_in, const int* in_sizes, int n_in,
                              void* d_out, int out_size) {
    const float* x_addr  = (const float*)d_in[0];
    const float* x_tx    = (const float*)d_in[1];
    const int*   eat_s   = (const int*)d_in[2];
    const int*   eat_d   = (const int*)d_in[3];
    const int*   eta_s   = (const int*)d_in[4];
    const int*   eta_d   = (const int*)d_in[5];
    const int*   eaa_s   = (const int*)d_in[6];
    const int*   eaa_d   = (const int*)d_in[7];
    const float* pW1     = (const float*)d_in[8];
    const float* pb1     = (const float*)d_in[9];
    const float* pW23    = (const float*)d_in[10];
    const float* pb23    = (const float*)d_in[11];
    const float* att_src = (const float*)d_in[12];
    const float* att_dst = (const float*)d_in[13];
    const float* kW      = (const float*)d_in[14];
    const float* kb      = (const float*)d_in[15];
    const float* q       = (const float*)d_in[16];
    const float* linW    = (const float*)d_in[17];
    const float* linb    = (const float*)d_in[18];
    float* out = (float*)d_out;

    const int B = 256;
    int csrN[3] = { N_TX, N_ADDR, N_ADDR };
    const int* dsts[3] = { eat_d, eta_d, eaa_d };
    int Es[3] = { E_AT, E_TA, E_AA };

    // ---- build CSR once (topology shared across layers) ----
    k_zero_cnt<<<cdiv(N_TX, B), B>>>();
    for (int r = 0; r < 3; r++)
        k_hist<<<cdiv(Es[r], B), B>>>(dsts[r], Es[r], r);
    for (int r = 0; r < 3; r++) {
        int nb = cdiv(csrN[r], 4096);
        k_scan1<<<nb, 1024>>>(r, csrN[r]);
        k_scan2<<<1, 128>>>(r, nb);
        k_scan3<<<cdiv(csrN[r], B), B>>>(r, csrN[r]);
    }
    k_scatter<<<cdiv(E_AT, B), B>>>(eat_s, eat_d, E_AT, 0);
    k_scatter<<<cdiv(E_TA, B), B>>>(eta_s, eta_d, E_TA, 1);
    k_scatter<<<cdiv(E_AA, B), B>>>(eaa_s, eaa_d, E_AA, 2);

    const int W_TOT = N_TX + 2 * N_ADDR;  // 500000 warps

    // ---- layers ----
    for (int l = 0; l < 3; l++) {
        const float *Wa, *ba, *Wt, *bt;
        int F, useExt;
        if (l == 0) {
            Wa = pW1; Wt = pW1 + 64 * HID;
            ba = pb1; bt = pb1 + HID;
            F = 64; useExt = 1;
        } else {
            Wa = pW23 + (size_t)(l - 1) * 2 * HID * HID;
            Wt = Wa + HID * HID;
            ba = pb23 + (size_t)(l - 1) * 2 * HID;
            bt = ba + HID;
            F = HID; useExt = 0;
        }
        const float* asl = att_src + l * 96;
        const float* adl = att_dst + l * 96;
        k_layer_init<<<1, 64>>>();
        k_proj_fused<<<cdiv(N_ADDR * HID, B), B>>>(x_addr, useExt, 1, Wa, ba, asl, adl, N_ADDR, F);
        k_proj_fused<<<cdiv(N_TX * HID, B), B>>>(x_tx, useExt, 0, Wt, bt, asl, adl, N_TX, F);
        k_amax<<<dim3(64, 3), B>>>();

        k_agg_all<<<cdiv(W_TOT, 8), B>>>();

        k_semacc<<<dim3(148, 2), B>>>(kW + (size_t)l * HID * HID, kb + l * HID);
        k_attn<<<1, 32>>>(q + l * HID);
        k_mix<<<cdiv(N_ADDR * HID, B), B>>>();
    }
    k_lin<<<cdiv(N_ADDR, B), B>>>(linW, linb, out);
}

// round 5
// speedup vs baseline: 2.5444x; 1.6454x over previous
#include <cuda_runtime.h>
#include <math.h>

#define N_ADDR 150000
#define N_TX   200000
#define HID    32
#define HEADS  4
#define E_AT   1000000
#define E_TA   1000000
#define E_AA   500000
#define E_TOT  (E_AT + E_TA + E_AA)

// ---------------- scratch (device globals; no allocations allowed) ----------------
__device__ __align__(16) float g_ha[(size_t)N_ADDR * HID];
__device__ __align__(16) float g_ht[(size_t)N_TX * HID];
__device__ __align__(16) float g_a [(size_t)N_ADDR * HID];
__device__ __align__(16) float g_t [(size_t)N_TX * HID];

__device__ __align__(16) float g_oa1[(size_t)N_ADDR * HID];
__device__ __align__(16) float g_oa2[(size_t)N_ADDR * HID];

__device__ __align__(16) float g_asA0[(size_t)N_ADDR * HEADS];
__device__ __align__(16) float g_asA2[(size_t)N_ADDR * HEADS];
__device__ __align__(16) float g_adA1[(size_t)N_ADDR * HEADS];
__device__ __align__(16) float g_adA2[(size_t)N_ADDR * HEADS];
__device__ __align__(16) float g_asT [(size_t)N_TX * HEADS];
__device__ __align__(16) float g_adT [(size_t)N_TX * HEADS];

// CSR structures (built once per launch; topology shared by all 3 layers)
__device__ int g_cnt[3][N_TX];
__device__ int g_off[3][N_TX + 1];
__device__ int g_cur[3][N_TX];
__device__ int g_bsum[3][128];
__device__ int g_csr0[E_AT];
__device__ int g_csr1[E_TA];
__device__ int g_csr2[E_AA];

// zero-initialized at module load; k_attn re-zeroes them after each use so
// every layer (and every graph replay) starts from zero.
__device__ unsigned g_gmax[3 * HEADS];
__device__ float g_sem[2 * HID];
__device__ float g_attn[2];

// ---------------- helpers ----------------
__device__ __forceinline__ unsigned fenc(float x) {
    unsigned b = __float_as_uint(x);
    return (b & 0x80000000u) ? ~b : (b | 0x80000000u);
}
__device__ __forceinline__ float fdec(unsigned u) {
    return (u & 0x80000000u) ? __uint_as_float(u & 0x7FFFFFFFu)
                             : __uint_as_float(~u);
}
__device__ __forceinline__ float lrelu(float l) { return l >= 0.f ? l : 0.2f * l; }
static inline int cdiv(int a, int b) { return (a + b - 1) / b; }

// ---------------- CSR build ----------------
__global__ void k_zero_cnt() {
    int i = blockIdx.x * blockDim.x + threadIdx.x;
    if (i < N_TX) g_cnt[0][i] = 0;
    if (i < N_ADDR) { g_cnt[1][i] = 0; g_cnt[2][i] = 0; }
}

__global__ void k_hist_all(const int* __restrict__ d0, const int* __restrict__ d1,
                           const int* __restrict__ d2) {
    int e = blockIdx.x * blockDim.x + threadIdx.x;
    if (e < E_AT) atomicAdd(&g_cnt[0][d0[e]], 1);
    else if (e < E_AT + E_TA) atomicAdd(&g_cnt[1][d1[e - E_AT]], 1);
    else if (e < E_TOT) atomicAdd(&g_cnt[2][d2[e - E_AT - E_TA]], 1);
}

// block-level exclusive scan: 1024 threads x 4 elements; blockIdx.y = relation
__global__ void k_scan1() {
    __shared__ int ws[32];
    int rel = blockIdx.y;
    int N = (rel == 0) ? N_TX : N_ADDR;
    const int* cnt = g_cnt[rel];
    int* off = g_off[rel];
    int t = threadIdx.x, lane = t & 31, wid = t >> 5;
    int base = blockIdx.x * 4096 + t * 4;
    int v0 = (base + 0 < N) ? cnt[base + 0] : 0;
    int v1 = (base + 1 < N) ? cnt[base + 1] : 0;
    int v2 = (base + 2 < N) ? cnt[base + 2] : 0;
    int v3 = (base + 3 < N) ? cnt[base + 3] : 0;
    int tsum = v0 + v1 + v2 + v3;
    int x = tsum;
    for (int o = 1; o < 32; o <<= 1) {
        int y = __shfl_up_sync(0xffffffffu, x, o);
        if (lane >= o) x += y;
    }
    if (lane == 31) ws[wid] = x;
    __syncthreads();
    if (wid == 0) {
        int w = ws[lane];
        for (int o = 1; o < 32; o <<= 1) {
            int y = __shfl_up_sync(0xffffffffu, w, o);
            if (lane >= o) w += y;
        }
        ws[lane] = w;
    }
    __syncthreads();
    int excl = x - tsum + (wid > 0 ? ws[wid - 1] : 0);
    if (base + 0 < N) off[base + 0] = excl;
    if (base + 1 < N) off[base + 1] = excl + v0;
    if (base + 2 < N) off[base + 2] = excl + v0 + v1;
    if (base + 3 < N) off[base + 3] = excl + v0 + v1 + v2;
    if (t == 1023) g_bsum[rel][blockIdx.x] = excl + tsum;
}

__global__ void k_scan2() {
    __shared__ int sh[128];
    int rel = blockIdx.y;
    const int nb = 49;
    int t = threadIdx.x;
    int orig = (t < nb) ? g_bsum[rel][t] : 0;
    sh[t] = orig;
    __syncthreads();
    for (int o = 1; o < 128; o <<= 1) {
        int v = (t >= o) ? sh[t - o] : 0;
        __syncthreads();
        sh[t] += v;
        __syncthreads();
    }
    if (t < nb) g_bsum[rel][t] = sh[t] - orig;
}

__global__ void k_scan3() {
    int rel = blockIdx.y;
    int N = (rel == 0) ? N_TX : N_ADDR;
    int i = blockIdx.x * blockDim.x + threadIdx.x;
    if (i >= N) return;
    int o = g_off[rel][i] + g_bsum[rel][i >> 12];
    g_off[rel][i] = o;
    g_cur[rel][i] = o;
    if (i == N - 1) g_off[rel][N] = o + g_cnt[rel][i];
}

// csr selected in device code (host-side __device__ symbol = wrong address)
__global__ void k_scatter_all(const int* __restrict__ s0, const int* __restrict__ d0,
                              const int* __restrict__ s1, const int* __restrict__ d1,
                              const int* __restrict__ s2, const int* __restrict__ d2) {
    int e = blockIdx.x * blockDim.x + threadIdx.x;
    if (e < E_AT) {
        int p = atomicAdd(&g_cur[0][d0[e]], 1);
        g_csr0[p] = s0[e];
    } else if (e < E_AT + E_TA) {
        int i = e - E_AT;
        int p = atomicAdd(&g_cur[1][d1[i]], 1);
        g_csr1[p] = s1[i];
    } else if (e < E_TOT) {
        int i = e - E_AT - E_TA;
        int p = atomicAdd(&g_cur[2][d2[i]], 1);
        g_csr2[p] = s2[i];
    }
}

// ---------------- per-layer kernels ----------------

// fused projection (both node types) + node-level attention dot products.
// one warp per node, lane = channel.
__global__ void k_proj_all(const float* __restrict__ xa, const float* __restrict__ xt,
                           int useExt,
                           const float* __restrict__ Wa, const float* __restrict__ ba,
                           const float* __restrict__ Wt, const float* __restrict__ bt,
                           const float* __restrict__ asl, const float* __restrict__ adl,
                           int F) {
    __shared__ float sWa[64 * HID], sWt[64 * HID];
    __shared__ float sba[HID], sbt[HID], sv[6][HID];
    int tid = threadIdx.x;
    for (int i = tid; i < F * HID; i += blockDim.x) { sWa[i] = Wa[i]; sWt[i] = Wt[i]; }
    if (tid < HID) {
        sba[tid] = ba[tid]; sbt[tid] = bt[tid];
        sv[0][tid] = asl[tid];        // rel0 src (addr)
        sv[1][tid] = asl[64 + tid];   // rel2 src (addr)
        sv[2][tid] = adl[32 + tid];   // rel1 dst (addr)
        sv[3][tid] = adl[64 + tid];   // rel2 dst (addr)
        sv[4][tid] = asl[32 + tid];   // rel1 src (tx)
        sv[5][tid] = adl[tid];        // rel0 dst (tx)
    }
    __syncthreads();

    int gw = blockIdx.x * (blockDim.x >> 5) + (tid >> 5);
    int c = tid & 31;
    if (gw >= N_ADDR + N_TX) return;
    bool isA = gw < N_ADDR;
    int n = isA ? gw : gw - N_ADDR;
    const float* x = isA ? (useExt ? xa : (const float*)g_a)
                         : (useExt ? xt : (const float*)g_t);
    const float* sW = isA ? sWa : sWt;
    float acc = isA ? sba[c] : sbt[c];
    const float4* xr4 = (const float4*)(x + (size_t)n * F);
    for (int k4 = 0; k4 < (F >> 2); k4++) {
        float4 v = xr4[k4];
        acc += v.x * sW[(4 * k4 + 0) * HID + c];
        acc += v.y * sW[(4 * k4 + 1) * HID + c];
        acc += v.z * sW[(4 * k4 + 2) * HID + c];
        acc += v.w * sW[(4 * k4 + 3) * HID + c];
    }
    (isA ? g_ha : g_ht)[(size_t)n * HID + c] = acc;

    int h = c >> 3;
    float p0, p1, p2 = 0.f, p3 = 0.f;
    if (isA) {
        p0 = acc * sv[0][c]; p1 = acc * sv[1][c];
        p2 = acc * sv[2][c]; p3 = acc * sv[3][c];
    } else {
        p0 = acc * sv[4][c]; p1 = acc * sv[5][c];
    }
#pragma unroll
    for (int o = 4; o > 0; o >>= 1) {
        p0 += __shfl_xor_sync(0xffffffffu, p0, o);
        p1 += __shfl_xor_sync(0xffffffffu, p1, o);
        p2 += __shfl_xor_sync(0xffffffffu, p2, o);
        p3 += __shfl_xor_sync(0xffffffffu, p3, o);
    }
    if ((c & 7) == 0) {
        if (isA) {
            g_asA0[(size_t)n * 4 + h] = p0;
            g_asA2[(size_t)n * 4 + h] = p1;
            g_adA1[(size_t)n * 4 + h] = p2;
            g_adA2[(size_t)n * 4 + h] = p3;
        } else {
            g_asT[(size_t)n * 4 + h] = p0;
            g_adT[(size_t)n * 4 + h] = p1;
        }
    }
}

// global per-head max of alpha_src per relation (softmax upper bound)
__global__ void k_amax() {
    int r = blockIdx.y;
    const float4* A; int N;
    if (r == 0)      { A = (const float4*)g_asA0; N = N_ADDR; }
    else if (r == 1) { A = (const float4*)g_asT;  N = N_TX; }
    else             { A = (const float4*)g_asA2; N = N_ADDR; }
    const float NEG = __int_as_float(0xff800000);
    float4 m = make_float4(NEG, NEG, NEG, NEG);
    for (int i = blockIdx.x * blockDim.x + threadIdx.x; i < N;
         i += gridDim.x * blockDim.x) {
        float4 v = A[i];
        m.x = fmaxf(m.x, v.x); m.y = fmaxf(m.y, v.y);
        m.z = fmaxf(m.z, v.z); m.w = fmaxf(m.w, v.w);
    }
#pragma unroll
    for (int o = 16; o > 0; o >>= 1) {
        m.x = fmaxf(m.x, __shfl_xor_sync(0xffffffffu, m.x, o));
        m.y = fmaxf(m.y, __shfl_xor_sync(0xffffffffu, m.y, o));
        m.z = fmaxf(m.z, __shfl_xor_sync(0xffffffffu, m.z, o));
        m.w = fmaxf(m.w, __shfl_xor_sync(0xffffffffu, m.w, o));
    }
    __shared__ float4 sm[8];
    int lane = threadIdx.x & 31, wid = threadIdx.x >> 5;
    if (lane == 0) sm[wid] = m;
    __syncthreads();
    if (threadIdx.x < 8) {
        float4 v = sm[threadIdx.x];
#pragma unroll
        for (int o = 4; o > 0; o >>= 1) {
            v.x = fmaxf(v.x, __shfl_xor_sync(0xffu, v.x, o));
            v.y = fmaxf(v.y, __shfl_xor_sync(0xffu, v.y, o));
            v.z = fmaxf(v.z, __shfl_xor_sync(0xffu, v.z, o));
            v.w = fmaxf(v.w, __shfl_xor_sync(0xffu, v.w, o));
        }
        if (threadIdx.x == 0) {
            atomicMax(&g_gmax[r * 4 + 0], fenc(v.x));
            atomicMax(&g_gmax[r * 4 + 1], fenc(v.y));
            atomicMax(&g_gmax[r * 4 + 2], fenc(v.z));
            atomicMax(&g_gmax[r * 4 + 3], fenc(v.w));
        }
    }
}

// fused gather aggregation for all 3 relations. one warp per dst node;
// neighbor indices prefetched with one coalesced load (deg<=32 covers ~all
// nodes), then 4 edges processed in parallel per iteration (8 lanes/edge).
__global__ void k_agg_all() {
    int gw = blockIdx.x * (blockDim.x >> 5) + (threadIdx.x >> 5);
    int lane = threadIdx.x & 31;
    int rel, node;
    if (gw < N_TX) { rel = 0; node = gw; }
    else if (gw < N_TX + N_ADDR) { rel = 1; node = gw - N_TX; }
    else if (gw < N_TX + 2 * N_ADDR) { rel = 2; node = gw - N_TX - N_ADDR; }
    else return;

    const int* off; const int* csr; const float* as_; const float* ad_;
    const float* hs; float* outp;
    if (rel == 0)      { off = g_off[0]; csr = g_csr0; as_ = g_asA0; ad_ = g_adT;  hs = g_ha; outp = g_t; }
    else if (rel == 1) { off = g_off[1]; csr = g_csr1; as_ = g_asT;  ad_ = g_adA1; hs = g_ht; outp = g_oa1; }
    else               { off = g_off[2]; csr = g_csr2; as_ = g_asA2; ad_ = g_adA2; hs = g_ha; outp = g_oa2; }

    int start = off[node], end = off[node + 1];
    int deg = end - start;
    int c4 = lane & 7, g = lane >> 3, h = c4 >> 1;
    float* orow = outp + (size_t)node * HID;
    if (deg == 0) {
        if (lane < 8) ((float4*)orow)[c4] = make_float4(0.f, 0.f, 0.f, 0.f);
        return;
    }
    float adv = ad_[(size_t)node * 4 + h];
    float m = lrelu(fdec(g_gmax[rel * 4 + h]) + adv);  // >= all edge logits

    int idx = (lane < deg) ? csr[start + lane] : 0;    // coalesced prefetch

    float4 acc = make_float4(0.f, 0.f, 0.f, 0.f);
    float ssum = 0.f;
    int dmain = min(deg, 32);
    for (int j0 = 0; j0 < dmain; j0 += 4) {
        int el = j0 + g;
        int s = __shfl_sync(0xffffffffu, idx, el & 31);  // full-warp shfl
        if (el < dmain) {
            float a = as_[(size_t)s * 4 + h];
            float w = __expf(lrelu(a + adv) - m);
            float4 f = *(const float4*)(hs + (size_t)s * HID + c4 * 4);
            acc.x += w * f.x; acc.y += w * f.y;
            acc.z += w * f.z; acc.w += w * f.w;
            ssum += w;
        }
    }
    // extremely rare: degree > 32
    for (int base = start + 32; base < end; base += 4) {
        int e = base + g;
        if (e < end) {
            int s = csr[e];
            float a = as_[(size_t)s * 4 + h];
            float w = __expf(lrelu(a + adv) - m);
            float4 f = *(const float4*)(hs + (size_t)s * HID + c4 * 4);
            acc.x += w * f.x; acc.y += w * f.y;
            acc.z += w * f.z; acc.w += w * f.w;
            ssum += w;
        }
    }
#pragma unroll
    for (int o = 8; o <= 16; o <<= 1) {
        acc.x += __shfl_xor_sync(0xffffffffu, acc.x, o);
        acc.y += __shfl_xor_sync(0xffffffffu, acc.y, o);
        acc.z += __shfl_xor_sync(0xffffffffu, acc.z, o);
        acc.w += __shfl_xor_sync(0xffffffffu, acc.w, o);
        ssum  += __shfl_xor_sync(0xffffffffu, ssum, o);
    }
    if (lane < 8) {
        float inv = 1.f / (ssum + 1e-16f);
        ((float4*)orow)[c4] = make_float4(fmaxf(acc.x * inv, 0.f),
                                          fmaxf(acc.y * inv, 0.f),
                                          fmaxf(acc.z * inv, 0.f),
                                          fmaxf(acc.w * inv, 0.f));
    }
}

// semantic accumulation: warp per node (coalesced), lane = channel.
__global__ void k_semacc(const float* __restrict__ kWl, const float* __restrict__ kbl) {
    int r = blockIdx.y;
    const float* O = (r == 0) ? (const float*)g_oa1 : (const float*)g_oa2;
    __shared__ float sW[HID * HID];
    __shared__ float sb_[HID];
    __shared__ float red[HID];
    int tid = threadIdx.x, lane = tid & 31, wid = tid >> 5;
    for (int i = tid; i < HID * HID; i += blockDim.x) sW[i] = kWl[i];
    if (tid < HID) { sb_[tid] = kbl[tid]; red[tid] = 0.f; }
    __syncthreads();

    float acc = 0.f;
    int wstride = gridDim.x * (blockDim.x >> 5);
    for (int n = blockIdx.x * (blockDim.x >> 5) + wid; n < N_ADDR; n += wstride) {
        float x = O[(size_t)n * HID + lane];
        float dsum = sb_[lane];
#pragma unroll
        for (int k = 0; k < HID; k++)
            dsum += __shfl_sync(0xffffffffu, x, k) * sW[k * HID + lane];
        acc += tanhf(dsum);
    }
    atomicAdd(&red[lane], acc);
    __syncthreads();
    if (tid < HID) atomicAdd(&g_sem[r * HID + tid], red[tid]);
}

// softmax over 2 relation scores; also resets g_sem/g_gmax for the next
// layer (and next graph replay — first run relies on static zero-init).
__global__ void k_attn(const float* __restrict__ q) {
    int c = threadIdx.x;
    const float inv = 1.0f / (float)N_ADDR;
    float qc = q[c];
    float p0 = g_sem[c] * inv * qc;
    float p1 = g_sem[HID + c] * inv * qc;
    for (int o = 16; o > 0; o >>= 1) {
        p0 += __shfl_xor_sync(0xffffffffu, p0, o);
        p1 += __shfl_xor_sync(0xffffffffu, p1, o);
    }
    if (c == 0) {
        float m = fmaxf(p0, p1);
        float e0 = __expf(p0 - m), e1 = __expf(p1 - m);
        float is = 1.f / (e0 + e1);
        g_attn[0] = e0 * is;
        g_attn[1] = e1 * is;
    }
    __syncwarp();
    g_sem[c] = 0.f;
    g_sem[HID + c] = 0.f;
    if (c < 3 * HEADS) g_gmax[c] = 0u;
}

__global__ void k_mix() {
    int idx = blockIdx.x * blockDim.x + threadIdx.x;
    if (idx >= N_ADDR * HID) return;
    float a0 = g_attn[0], a1 = g_attn[1];
    g_a[idx] = fmaxf(a0 * g_oa1[idx] + a1 * g_oa2[idx], 0.f);
}

// final linear: warp per node (coalesced row read), shfl reduce.
__global__ void k_lin(const float* __restrict__ linW, const float* __restrict__ linb,
                      float* __restrict__ out) {
    int gw = blockIdx.x * (blockDim.x >> 5) + (threadIdx.x >> 5);
    int c = threadIdx.x & 31;
    if (gw >= N_ADDR) return;
    float v = g_a[(size_t)gw * HID + c];
    float s0 = v * linW[c * 2];
    float s1 = v * linW[c * 2 + 1];
#pragma unroll
    for (int o = 16; o > 0; o >>= 1) {
        s0 += __shfl_xor_sync(0xffffffffu, s0, o);
        s1 += __shfl_xor_sync(0xffffffffu, s1, o);
    }
    if (c == 0)
        *(float2*)(out + (size_t)gw * 2) = make_float2(s0 + linb[0], s1 + linb[1]);
}

// ---------------- host ----------------
extern "C" void kernel_launch(void* const* d_in, const int* in_sizes, int n_in,
                              void* d_out, int out_size) {
    const float* x_addr  = (const float*)d_in[0];
    const float* x_tx    = (const float*)d_in[1];
    const int*   eat_s   = (const int*)d_in[2];
    const int*   eat_d   = (const int*)d_in[3];
    const int*   eta_s   = (const int*)d_in[4];
    const int*   eta_d   = (const int*)d_in[5];
    const int*   eaa_s   = (const int*)d_in[6];
    const int*   eaa_d   = (const int*)d_in[7];
    const float* pW1     = (const float*)d_in[8];
    const float* pb1     = (const float*)d_in[9];
    const float* pW23    = (const float*)d_in[10];
    const float* pb23    = (const float*)d_in[11];
    const float* att_src = (const float*)d_in[12];
    const float* att_dst = (const float*)d_in[13];
    const float* kW      = (const float*)d_in[14];
    const float* kb      = (const float*)d_in[15];
    const float* q       = (const float*)d_in[16];
    const float* linW    = (const float*)d_in[17];
    const float* linb    = (const float*)d_in[18];
    float* out = (float*)d_out;

    const int B = 256;
    const int NODES = N_ADDR + N_TX;      // 350000
    const int W_TOT = N_TX + 2 * N_ADDR;  // 500000 agg warps

    // ---- CSR build (once; topology shared across layers). k_proj_all of
    // layer 0 is independent and placed as the 4th launch (ncu window). ----
    k_zero_cnt<<<cdiv(N_TX, B), B>>>();
    k_hist_all<<<cdiv(E_TOT, B), B>>>(eat_d, eta_d, eaa_d);
    k_scan1<<<dim3(49, 3), 1024>>>();
    k_proj_all<<<cdiv(NODES, 8), B>>>(x_addr, x_tx, 1,
                                      pW1, pb1, pW1 + 64 * HID, pb1 + HID,
                                      att_src, att_dst, 64);
    k_scan2<<<dim3(1, 3), 128>>>();
    k_scan3<<<dim3(cdiv(N_TX, B), 3), B>>>();
    k_scatter_all<<<cdiv(E_TOT, B), B>>>(eat_s, eat_d, eta_s, eta_d, eaa_s, eaa_d);

    // ---- layers ----
    for (int l = 0; l < 3; l++) {
        if (l > 0) {
            const float* Wa = pW23 + (size_t)(l - 1) * 2 * HID * HID;
            const float* ba = pb23 + (size_t)(l - 1) * 2 * HID;
            k_proj_all<<<cdiv(NODES, 8), B>>>(x_addr, x_tx, 0,
                                              Wa, ba, Wa + HID * HID, ba + HID,
                                              att_src + l * 96, att_dst + l * 96, HID);
        }
        k_amax<<<dim3(64, 3), B>>>();
        k_agg_all<<<cdiv(W_TOT, 8), B>>>();
        k_semacc<<<dim3(148, 2), B>>>(kW + (size_t)l * HID * HID, kb + l * HID);
        k_attn<<<1, 32>>>(q + l * HID);
        k_mix<<<cdiv(N_ADDR * HID, B), B>>>();
    }
    k_lin<<<cdiv(N_ADDR, 8), B>>>(linW, linb, out);
}

// round 7
// speedup vs baseline: 3.0474x; 1.1977x over previous
#include <cuda_runtime.h>
#include <math.h>

#define N_ADDR 150000
#define N_TX   200000
#define HID    32
#define HEADS  4
#define E_AT   1000000
#define E_TA   1000000
#define E_AA   500000
#define E_TOT  (E_AT + E_TA + E_AA)
#define NODES  (N_ADDR + N_TX)

// ---------------- scratch (device globals; no allocations allowed) ----------------
__device__ __align__(16) float g_ha[(size_t)N_ADDR * HID];
__device__ __align__(16) float g_ht[(size_t)N_TX * HID];
__device__ __align__(16) float g_a [(size_t)N_ADDR * HID];
__device__ __align__(16) float g_t [(size_t)N_TX * HID];

__device__ __align__(16) float g_oa1[(size_t)N_ADDR * HID];
__device__ __align__(16) float g_oa2[(size_t)N_ADDR * HID];

__device__ __align__(16) float g_asA0[(size_t)N_ADDR * HEADS];
__device__ __align__(16) float g_asA2[(size_t)N_ADDR * HEADS];
__device__ __align__(16) float g_adA1[(size_t)N_ADDR * HEADS];
__device__ __align__(16) float g_adA2[(size_t)N_ADDR * HEADS];
__device__ __align__(16) float g_asT [(size_t)N_TX * HEADS];
__device__ __align__(16) float g_adT [(size_t)N_TX * HEADS];

// CSR structures (built once per launch; topology shared by all 3 layers)
__device__ int g_cnt[3][N_TX];
__device__ int g_off[3][N_TX + 1];
__device__ int g_cur[3][N_TX];
__device__ int g_bsum[3][128];
__device__ int g_csr0[E_AT];
__device__ int g_csr1[E_TA];
__device__ int g_csr2[E_AA];

// zero-initialized at module load; k_attn re-zeroes after each use so every
// layer (and every graph replay) starts from zero.
__device__ unsigned g_gmax[3 * HEADS];
__device__ float g_sem[2 * HID];
__device__ float g_attn[2];

// ---------------- helpers ----------------
__device__ __forceinline__ unsigned fenc(float x) {
    unsigned b = __float_as_uint(x);
    return (b & 0x80000000u) ? ~b : (b | 0x80000000u);
}
__device__ __forceinline__ float fdec(unsigned u) {
    return (u & 0x80000000u) ? __uint_as_float(u & 0x7FFFFFFFu)
                             : __uint_as_float(~u);
}
__device__ __forceinline__ float lrelu(float l) { return l >= 0.f ? l : 0.2f * l; }
static inline int cdiv(int a, int b) { return (a + b - 1) / b; }

// ---------------- CSR build ----------------
__global__ void k_zero_cnt() {
    int i = blockIdx.x * blockDim.x + threadIdx.x;
    if (i < N_TX) g_cnt[0][i] = 0;
    if (i < N_ADDR) { g_cnt[1][i] = 0; g_cnt[2][i] = 0; }
}

__global__ void k_hist_all(const int* __restrict__ d0, const int* __restrict__ d1,
                           const int* __restrict__ d2) {
    int e = blockIdx.x * blockDim.x + threadIdx.x;
    if (e < E_AT) atomicAdd(&g_cnt[0][d0[e]], 1);
    else if (e < E_AT + E_TA) atomicAdd(&g_cnt[1][d1[e - E_AT]], 1);
    else if (e < E_TOT) atomicAdd(&g_cnt[2][d2[e - E_AT - E_TA]], 1);
}

// block-level exclusive scan: 1024 threads x 4 elements; blockIdx.y = relation
__global__ void k_scan1() {
    __shared__ int ws[32];
    int rel = blockIdx.y;
    int N = (rel == 0) ? N_TX : N_ADDR;
    const int* cnt = g_cnt[rel];
    int* off = g_off[rel];
    int t = threadIdx.x, lane = t & 31, wid = t >> 5;
    int base = blockIdx.x * 4096 + t * 4;
    int v0 = (base + 0 < N) ? cnt[base + 0] : 0;
    int v1 = (base + 1 < N) ? cnt[base + 1] : 0;
    int v2 = (base + 2 < N) ? cnt[base + 2] : 0;
    int v3 = (base + 3 < N) ? cnt[base + 3] : 0;
    int tsum = v0 + v1 + v2 + v3;
    int x = tsum;
    for (int o = 1; o < 32; o <<= 1) {
        int y = __shfl_up_sync(0xffffffffu, x, o);
        if (lane >= o) x += y;
    }
    if (lane == 31) ws[wid] = x;
    __syncthreads();
    if (wid == 0) {
        int w = ws[lane];
        for (int o = 1; o < 32; o <<= 1) {
            int y = __shfl_up_sync(0xffffffffu, w, o);
            if (lane >= o) w += y;
        }
        ws[lane] = w;
    }
    __syncthreads();
    int excl = x - tsum + (wid > 0 ? ws[wid - 1] : 0);
    if (base + 0 < N) off[base + 0] = excl;
    if (base + 1 < N) off[base + 1] = excl + v0;
    if (base + 2 < N) off[base + 2] = excl + v0 + v1;
    if (base + 3 < N) off[base + 3] = excl + v0 + v1 + v2;
    if (t == 1023) g_bsum[rel][blockIdx.x] = excl + tsum;
}

__global__ void k_scan2() {
    __shared__ int sh[128];
    int rel = blockIdx.y;
    const int nb = 49;
    int t = threadIdx.x;
    int orig = (t < nb) ? g_bsum[rel][t] : 0;
    sh[t] = orig;
    __syncthreads();
    for (int o = 1; o < 128; o <<= 1) {
        int v = (t >= o) ? sh[t - o] : 0;
        __syncthreads();
        sh[t] += v;
        __syncthreads();
    }
    if (t < nb) g_bsum[rel][t] = sh[t] - orig;
}

__global__ void k_scan3() {
    int rel = blockIdx.y;
    int N = (rel == 0) ? N_TX : N_ADDR;
    int i = blockIdx.x * blockDim.x + threadIdx.x;
    if (i >= N) return;
    int o = g_off[rel][i] + g_bsum[rel][i >> 12];
    g_off[rel][i] = o;
    g_cur[rel][i] = o;
    if (i == N - 1) g_off[rel][N] = o + g_cnt[rel][i];
}

// csr selected in device code (host-side __device__ symbol = wrong address)
__global__ void k_scatter_all(const int* __restrict__ s0, const int* __restrict__ d0,
                              const int* __restrict__ s1, const int* __restrict__ d1,
                              const int* __restrict__ s2, const int* __restrict__ d2) {
    int e = blockIdx.x * blockDim.x + threadIdx.x;
    if (e < E_AT) {
        int p = atomicAdd(&g_cur[0][d0[e]], 1);
        g_csr0[p] = s0[e];
    } else if (e < E_AT + E_TA) {
        int i = e - E_AT;
        int p = atomicAdd(&g_cur[1][d1[i]], 1);
        g_csr1[p] = s1[i];
    } else if (e < E_TOT) {
        int i = e - E_AT - E_TA;
        int p = atomicAdd(&g_cur[2][d2[i]], 1);
        g_csr2[p] = s2[i];
    }
}

// ---------------- per-layer kernels ----------------

// fused projection (both node types) + node-level attention dot products.
// 4 nodes per warp; 8 lanes per node; each lane owns a float4 of 4 output
// channels -> 16 FFMA per LDS.128 (vs 1 before; kernel was LDS-bound).
__global__ void k_proj_all(const float* __restrict__ xa, const float* __restrict__ xt,
                           int useExt,
                           const float* __restrict__ Wa, const float* __restrict__ ba,
                           const float* __restrict__ Wt, const float* __restrict__ bt,
                           const float* __restrict__ asl, const float* __restrict__ adl,
                           int F) {
    __shared__ float4 sWa[64 * 8], sWt[64 * 8];   // row k: 8 float4s (32 channels)
    __shared__ float4 sba4[8], sbt4[8], sv4[6][8];
    int tid = threadIdx.x;
    for (int i = tid; i < F * 8; i += blockDim.x) {
        sWa[i] = ((const float4*)Wa)[i];
        sWt[i] = ((const float4*)Wt)[i];
    }
    if (tid < 8) {
        sba4[tid] = ((const float4*)ba)[tid];
        sbt4[tid] = ((const float4*)bt)[tid];
    }
    if (tid < 48) {
        int r = tid >> 3, cc = tid & 7;
        const float* p = (r == 0) ? asl : (r == 1) ? asl + 64 :
                         (r == 2) ? adl + 32 : (r == 3) ? adl + 64 :
                         (r == 4) ? asl + 32 : adl;
        sv4[r][cc] = ((const float4*)p)[cc];
    }
    __syncthreads();

    int warp = blockIdx.x * (blockDim.x >> 5) + (tid >> 5);
    int lane = tid & 31;
    int g = lane >> 3, c4 = lane & 7;
    int node = warp * 4 + g;
    if (node >= NODES) node = NODES - 1;  // duplicate work writes identical values
    bool isA = node < N_ADDR;
    int n = isA ? node : node - N_ADDR;

    const float* x = isA ? (useExt ? xa : (const float*)g_a)
                         : (useExt ? xt : (const float*)g_t);
    const float4* xr4 = (const float4*)(x + (size_t)n * F);
    const float4* sW = isA ? sWa : sWt;
    float4 acc = isA ? sba4[c4] : sbt4[c4];

    int K4 = F >> 2;
    for (int k4 = 0; k4 < K4; k4++) {
        float4 xv = xr4[k4];                 // 8-lane broadcast load
        float4 w0 = sW[(4 * k4 + 0) * 8 + c4];
        float4 w1 = sW[(4 * k4 + 1) * 8 + c4];
        float4 w2 = sW[(4 * k4 + 2) * 8 + c4];
        float4 w3 = sW[(4 * k4 + 3) * 8 + c4];
        acc.x += xv.x * w0.x + xv.y * w1.x + xv.z * w2.x + xv.w * w3.x;
        acc.y += xv.x * w0.y + xv.y * w1.y + xv.z * w2.y + xv.w * w3.y;
        acc.z += xv.x * w0.z + xv.y * w1.z + xv.z * w2.z + xv.w * w3.z;
        acc.w += xv.x * w0.w + xv.y * w1.w + xv.z * w2.w + xv.w * w3.w;
    }
    ((float4*)((isA ? g_ha : g_ht) + (size_t)n * HID))[c4] = acc;

    // attention dot products: lane holds channels 4*c4..4*c4+3; head h = c4>>1.
    float4 s0 = sv4[isA ? 0 : 4][c4];
    float4 s1 = sv4[isA ? 1 : 5][c4];
    float p0 = acc.x * s0.x + acc.y * s0.y + acc.z * s0.z + acc.w * s0.w;
    float p1 = acc.x * s1.x + acc.y * s1.y + acc.z * s1.z + acc.w * s1.w;
    float p2 = 0.f, p3 = 0.f;
    if (isA) {
        float4 s2 = sv4[2][c4], s3 = sv4[3][c4];
        p2 = acc.x * s2.x + acc.y * s2.y + acc.z * s2.z + acc.w * s2.w;
        p3 = acc.x * s3.x + acc.y * s3.y + acc.z * s3.z + acc.w * s3.w;
    }
    p0 += __shfl_xor_sync(0xffffffffu, p0, 1);
    p1 += __shfl_xor_sync(0xffffffffu, p1, 1);
    p2 += __shfl_xor_sync(0xffffffffu, p2, 1);
    p3 += __shfl_xor_sync(0xffffffffu, p3, 1);
    if ((c4 & 1) == 0) {
        int h = c4 >> 1;
        if (isA) {
            g_asA0[(size_t)n * 4 + h] = p0;
            g_asA2[(size_t)n * 4 + h] = p1;
            g_adA1[(size_t)n * 4 + h] = p2;
            g_adA2[(size_t)n * 4 + h] = p3;
        } else {
            g_asT[(size_t)n * 4 + h] = p0;
            g_adT[(size_t)n * 4 + h] = p1;
        }
    }
}

// global per-head max of alpha_src per relation (softmax upper bound)
__global__ void k_amax() {
    int r = blockIdx.y;
    const float4* A; int N;
    if (r == 0)      { A = (const float4*)g_asA0; N = N_ADDR; }
    else if (r == 1) { A = (const float4*)g_asT;  N = N_TX; }
    else             { A = (const float4*)g_asA2; N = N_ADDR; }
    const float NEG = __int_as_float(0xff800000);
    float4 m = make_float4(NEG, NEG, NEG, NEG);
    for (int i = blockIdx.x * blockDim.x + threadIdx.x; i < N;
         i += gridDim.x * blockDim.x) {
        float4 v = A[i];
        m.x = fmaxf(m.x, v.x); m.y = fmaxf(m.y, v.y);
        m.z = fmaxf(m.z, v.z); m.w = fmaxf(m.w, v.w);
    }
#pragma unroll
    for (int o = 16; o > 0; o >>= 1) {
        m.x = fmaxf(m.x, __shfl_xor_sync(0xffffffffu, m.x, o));
        m.y = fmaxf(m.y, __shfl_xor_sync(0xffffffffu, m.y, o));
        m.z = fmaxf(m.z, __shfl_xor_sync(0xffffffffu, m.z, o));
        m.w = fmaxf(m.w, __shfl_xor_sync(0xffffffffu, m.w, o));
    }
    __shared__ float4 sm[8];
    int lane = threadIdx.x & 31, wid = threadIdx.x >> 5;
    if (lane == 0) sm[wid] = m;
    __syncthreads();
    if (threadIdx.x < 8) {
        float4 v = sm[threadIdx.x];
#pragma unroll
        for (int o = 4; o > 0; o >>= 1) {
            v.x = fmaxf(v.x, __shfl_xor_sync(0xffu, v.x, o));
            v.y = fmaxf(v.y, __shfl_xor_sync(0xffu, v.y, o));
            v.z = fmaxf(v.z, __shfl_xor_sync(0xffu, v.z, o));
            v.w = fmaxf(v.w, __shfl_xor_sync(0xffu, v.w, o));
        }
        if (threadIdx.x == 0) {
            atomicMax(&g_gmax[r * 4 + 0], fenc(v.x));
            atomicMax(&g_gmax[r * 4 + 1], fenc(v.y));
            atomicMax(&g_gmax[r * 4 + 2], fenc(v.z));
            atomicMax(&g_gmax[r * 4 + 3], fenc(v.w));
        }
    }
}

// fused gather aggregation for all 3 relations. one warp per dst node;
// neighbor indices prefetched with one coalesced load (deg<=32 covers ~all
// nodes), then 4 edges processed in parallel per iteration (8 lanes/edge).
__global__ void k_agg_all() {
    int gw = blockIdx.x * (blockDim.x >> 5) + (threadIdx.x >> 5);
    int lane = threadIdx.x & 31;
    int rel, node;
    if (gw < N_TX) { rel = 0; node = gw; }
    else if (gw < N_TX + N_ADDR) { rel = 1; node = gw - N_TX; }
    else if (gw < N_TX + 2 * N_ADDR) { rel = 2; node = gw - N_TX - N_ADDR; }
    else return;

    const int* off; const int* csr; const float* as_; const float* ad_;
    const float* hs; float* outp;
    if (rel == 0)      { off = g_off[0]; csr = g_csr0; as_ = g_asA0; ad_ = g_adT;  hs = g_ha; outp = g_t; }
    else if (rel == 1) { off = g_off[1]; csr = g_csr1; as_ = g_asT;  ad_ = g_adA1; hs = g_ht; outp = g_oa1; }
    else               { off = g_off[2]; csr = g_csr2; as_ = g_asA2; ad_ = g_adA2; hs = g_ha; outp = g_oa2; }

    int start = off[node], end = off[node + 1];
    int deg = end - start;
    int c4 = lane & 7, g = lane >> 3, h = c4 >> 1;
    float* orow = outp + (size_t)node * HID;
    if (deg == 0) {
        if (lane < 8) ((float4*)orow)[c4] = make_float4(0.f, 0.f, 0.f, 0.f);
        return;
    }
    float adv = ad_[(size_t)node * 4 + h];
    float m = lrelu(fdec(g_gmax[rel * 4 + h]) + adv);  // >= all edge logits

    int idx = (lane < deg) ? csr[start + lane] : 0;    // coalesced prefetch

    float4 acc = make_float4(0.f, 0.f, 0.f, 0.f);
    float ssum = 0.f;
    int dmain = min(deg, 32);
    for (int j0 = 0; j0 < dmain; j0 += 4) {
        int el = j0 + g;
        int s = __shfl_sync(0xffffffffu, idx, el & 31);
        if (el < dmain) {
            float a = as_[(size_t)s * 4 + h];
            float w = __expf(lrelu(a + adv) - m);
            float4 f = *(const float4*)(hs + (size_t)s * HID + c4 * 4);
            acc.x += w * f.x; acc.y += w * f.y;
            acc.z += w * f.z; acc.w += w * f.w;
            ssum += w;
        }
    }
    for (int base = start + 32; base < end; base += 4) {   // rare deg > 32
        int e = base + g;
        if (e < end) {
            int s = csr[e];
            float a = as_[(size_t)s * 4 + h];
            float w = __expf(lrelu(a + adv) - m);
            float4 f = *(const float4*)(hs + (size_t)s * HID + c4 * 4);
            acc.x += w * f.x; acc.y += w * f.y;
            acc.z += w * f.z; acc.w += w * f.w;
            ssum += w;
        }
    }
#pragma unroll
    for (int o = 8; o <= 16; o <<= 1) {
        acc.x += __shfl_xor_sync(0xffffffffu, acc.x, o);
        acc.y += __shfl_xor_sync(0xffffffffu, acc.y, o);
        acc.z += __shfl_xor_sync(0xffffffffu, acc.z, o);
        acc.w += __shfl_xor_sync(0xffffffffu, acc.w, o);
        ssum  += __shfl_xor_sync(0xffffffffu, ssum, o);
    }
    if (lane < 8) {
        float inv = 1.f / (ssum + 1e-16f);
        ((float4*)orow)[c4] = make_float4(fmaxf(acc.x * inv, 0.f),
                                          fmaxf(acc.y * inv, 0.f),
                                          fmaxf(acc.z * inv, 0.f),
                                          fmaxf(acc.w * inv, 0.f));
    }
}

// semantic accumulation: warp per node (coalesced), lane = channel.
__global__ void k_semacc(const float* __restrict__ kWl, const float* __restrict__ kbl) {
    int r = blockIdx.y;
    const float* O = (r == 0) ? (const float*)g_oa1 : (const float*)g_oa2;
    __shared__ float sW[HID * HID];
    __shared__ float sb_[HID];
    __shared__ float red[HID];
    int tid = threadIdx.x, lane = tid & 31, wid = tid >> 5;
    for (int i = tid; i < HID * HID; i += blockDim.x) sW[i] = kWl[i];
    if (tid < HID) { sb_[tid] = kbl[tid]; red[tid] = 0.f; }
    __syncthreads();

    float acc = 0.f;
    int wstride = gridDim.x * (blockDim.x >> 5);
    for (int n = blockIdx.x * (blockDim.x >> 5) + wid; n < N_ADDR; n += wstride) {
        float x = O[(size_t)n * HID + lane];
        float dsum = sb_[lane];
#pragma unroll
        for (int k = 0; k < HID; k++)
            dsum += __shfl_sync(0xffffffffu, x, k) * sW[k * HID + lane];
        acc += tanhf(dsum);
    }
    atomicAdd(&red[lane], acc);
    __syncthreads();
    if (tid < HID) atomicAdd(&g_sem[r * HID + tid], red[tid]);
}

// softmax over 2 relation scores; also resets g_sem/g_gmax for next layer/replay
__global__ void k_attn(const float* __restrict__ q) {
    int c = threadIdx.x;
    const float inv = 1.0f / (float)N_ADDR;
    float qc = q[c];
    float p0 = g_sem[c] * inv * qc;
    float p1 = g_sem[HID + c] * inv * qc;
    for (int o = 16; o > 0; o >>= 1) {
        p0 += __shfl_xor_sync(0xffffffffu, p0, o);
        p1 += __shfl_xor_sync(0xffffffffu, p1, o);
    }
    if (c == 0) {
        float m = fmaxf(p0, p1);
        float e0 = __expf(p0 - m), e1 = __expf(p1 - m);
        float is = 1.f / (e0 + e1);
        g_attn[0] = e0 * is;
        g_attn[1] = e1 * is;
    }
    __syncwarp();
    g_sem[c] = 0.f;
    g_sem[HID + c] = 0.f;
    if (c < 3 * HEADS) g_gmax[c] = 0u;
}

__global__ void k_mix() {
    int idx = blockIdx.x * blockDim.x + threadIdx.x;
    if (idx >= N_ADDR * HID) return;
    float a0 = g_attn[0], a1 = g_attn[1];
    g_a[idx] = fmaxf(a0 * g_oa1[idx] + a1 * g_oa2[idx], 0.f);
}

// final linear: warp per node (coalesced row read), shfl reduce.
__global__ void k_lin(const float* __restrict__ linW, const float* __restrict__ linb,
                      float* __restrict__ out) {
    int gw = blockIdx.x * (blockDim.x >> 5) + (threadIdx.x >> 5);
    int c = threadIdx.x & 31;
    if (gw >= N_ADDR) return;
    float v = g_a[(size_t)gw * HID + c];
    float s0 = v * linW[c * 2];
    float s1 = v * linW[c * 2 + 1];
#pragma unroll
    for (int o = 16; o > 0; o >>= 1) {
        s0 += __shfl_xor_sync(0xffffffffu, s0, o);
        s1 += __shfl_xor_sync(0xffffffffu, s1, o);
    }
    if (c == 0)
        *(float2*)(out + (size_t)gw * 2) = make_float2(s0 + linb[0], s1 + linb[1]);
}

// ---------------- host ----------------
extern "C" void kernel_launch(void* const* d_in, const int* in_sizes, int n_in,
                              void* d_out, int out_size) {
    const float* x_addr  = (const float*)d_in[0];
    const float* x_tx    = (const float*)d_in[1];
    const int*   eat_s   = (const int*)d_in[2];
    const int*   eat_d   = (const int*)d_in[3];
    const int*   eta_s   = (const int*)d_in[4];
    const int*   eta_d   = (const int*)d_in[5];
    const int*   eaa_s   = (const int*)d_in[6];
    const int*   eaa_d   = (const int*)d_in[7];
    const float* pW1     = (const float*)d_in[8];
    const float* pb1     = (const float*)d_in[9];
    const float* pW23    = (const float*)d_in[10];
    const float* pb23    = (const float*)d_in[11];
    const float* att_src = (const float*)d_in[12];
    const float* att_dst = (const float*)d_in[13];
    const float* kW      = (const float*)d_in[14];
    const float* kb      = (const float*)d_in[15];
    const float* q       = (const float*)d_in[16];
    const float* linW    = (const float*)d_in[17];
    const float* linb    = (const float*)d_in[18];
    float* out = (float*)d_out;

    const int B = 256;
    const int W_TOT = N_TX + 2 * N_ADDR;        // 500000 agg warps
    const int PROJ_BLK = cdiv(NODES, 4 * 8);    // 4 nodes/warp, 8 warps/block

    // ---- CSR build (once). layer-0 k_proj_all placed 4th (ncu window -s 5
    // with -c 1 profiles around here; k_agg_all is 8th for next inspection) ----
    k_zero_cnt<<<cdiv(N_TX, B), B>>>();
    k_hist_all<<<cdiv(E_TOT, B), B>>>(eat_d, eta_d, eaa_d);
    k_scan1<<<dim3(49, 3), 1024>>>();
    k_proj_all<<<PROJ_BLK, B>>>(x_addr, x_tx, 1,
                                pW1, pb1, pW1 + 64 * HID, pb1 + HID,
                                att_src, att_dst, 64);
    k_scan2<<<dim3(1, 3), 128>>>();
    k_scan3<<<dim3(cdiv(N_TX, B), 3), B>>>();
    k_scatter_all<<<cdiv(E_TOT, B), B>>>(eat_s, eat_d, eta_s, eta_d, eaa_s, eaa_d);

    // ---- layers ----
    for (int l = 0; l < 3; l++) {
        if (l > 0) {
            const float* Wa = pW23 + (size_t)(l - 1) * 2 * HID * HID;
            const float* ba = pb23 + (size_t)(l - 1) * 2 * HID;
            k_proj_all<<<PROJ_BLK, B>>>(x_addr, x_tx, 0,
                                        Wa, ba, Wa + HID * HID, ba + HID,
                                        att_src + l * 96, att_dst + l * 96, HID);
        }
        k_amax<<<dim3(64, 3), B>>>();
        k_agg_all<<<cdiv(W_TOT, 8), B>>>();
        k_semacc<<<dim3(148, 2), B>>>(kW + (size_t)l * HID * HID, kb + l * HID);
        k_attn<<<1, 32>>>(q + l * HID);
        k_mix<<<cdiv(N_ADDR * HID, B), B>>>();
    }
    k_lin<<<cdiv(N_ADDR, 8), B>>>(linW, linb, out);
}

// round 8
// speedup vs baseline: 3.7241x; 1.2221x over previous
#include <cuda_runtime.h>
#include <math.h>

#define N_ADDR 150000
#define N_TX   200000
#define HID    32
#define HEADS  4
#define E_AT   1000000
#define E_TA   1000000
#define E_AA   500000
#define E_TOT  (E_AT + E_TA + E_AA)
#define NODES  (N_ADDR + N_TX)
#define W_TOT  (N_TX + 2 * N_ADDR)
#define PROJ_NPB 32

// ---------------- scratch (device globals; no allocations allowed) ----------------
__device__ __align__(16) float g_ha[(size_t)N_ADDR * HID];
__device__ __align__(16) float g_ht[(size_t)N_TX * HID];
__device__ __align__(16) float g_t [(size_t)N_TX * HID];

__device__ __align__(16) float g_oa1[(size_t)N_ADDR * HID];
__device__ __align__(16) float g_oa2[(size_t)N_ADDR * HID];

__device__ __align__(16) float g_asA0[(size_t)N_ADDR * HEADS];
__device__ __align__(16) float g_asA2[(size_t)N_ADDR * HEADS];
__device__ __align__(16) float g_adA1[(size_t)N_ADDR * HEADS];
__device__ __align__(16) float g_adA2[(size_t)N_ADDR * HEADS];
__device__ __align__(16) float g_asT [(size_t)N_TX * HEADS];
__device__ __align__(16) float g_adT [(size_t)N_TX * HEADS];

// CSR structures (built once per launch; topology shared by all 3 layers)
__device__ int g_cnt[3][N_TX];
__device__ int g_off[3][N_TX + 1];
__device__ int g_cur[3][N_TX];
__device__ int g_bsum[3][128];
__device__ int g_csr0[E_AT];
__device__ int g_csr1[E_TA];
__device__ int g_csr2[E_AA];

// zero-initialized at module load; k_attn re-zeroes after each use so every
// layer (and every graph replay) starts from zero.
__device__ unsigned g_gmax[3 * HEADS];
__device__ float g_sem[2 * HID];
__device__ float g_attn[2];

// ---------------- helpers ----------------
__device__ __forceinline__ unsigned fenc(float x) {
    unsigned b = __float_as_uint(x);
    return (b & 0x80000000u) ? ~b : (b | 0x80000000u);
}
__device__ __forceinline__ float fdec(unsigned u) {
    return (u & 0x80000000u) ? __uint_as_float(u & 0x7FFFFFFFu)
                             : __uint_as_float(~u);
}
__device__ __forceinline__ float lrelu(float l) { return l >= 0.f ? l : 0.2f * l; }
static inline int cdiv(int a, int b) { return (a + b - 1) / b; }

// ---------------- CSR build ----------------
__global__ void k_zero_cnt() {
    int i = blockIdx.x * blockDim.x + threadIdx.x;
    if (i < N_TX) g_cnt[0][i] = 0;
    if (i < N_ADDR) { g_cnt[1][i] = 0; g_cnt[2][i] = 0; }
}

__global__ void k_hist_all(const int* __restrict__ d0, const int* __restrict__ d1,
                           const int* __restrict__ d2) {
    int e = blockIdx.x * blockDim.x + threadIdx.x;
    if (e < E_AT) atomicAdd(&g_cnt[0][d0[e]], 1);
    else if (e < E_AT + E_TA) atomicAdd(&g_cnt[1][d1[e - E_AT]], 1);
    else if (e < E_TOT) atomicAdd(&g_cnt[2][d2[e - E_AT - E_TA]], 1);
}

// block-level exclusive scan: 1024 threads x 4 elements; blockIdx.y = relation
__global__ void k_scan1() {
    __shared__ int ws[32];
    int rel = blockIdx.y;
    int N = (rel == 0) ? N_TX : N_ADDR;
    const int* cnt = g_cnt[rel];
    int* off = g_off[rel];
    int t = threadIdx.x, lane = t & 31, wid = t >> 5;
    int base = blockIdx.x * 4096 + t * 4;
    int v0 = (base + 0 < N) ? cnt[base + 0] : 0;
    int v1 = (base + 1 < N) ? cnt[base + 1] : 0;
    int v2 = (base + 2 < N) ? cnt[base + 2] : 0;
    int v3 = (base + 3 < N) ? cnt[base + 3] : 0;
    int tsum = v0 + v1 + v2 + v3;
    int x = tsum;
    for (int o = 1; o < 32; o <<= 1) {
        int y = __shfl_up_sync(0xffffffffu, x, o);
        if (lane >= o) x += y;
    }
    if (lane == 31) ws[wid] = x;
    __syncthreads();
    if (wid == 0) {
        int w = ws[lane];
        for (int o = 1; o < 32; o <<= 1) {
            int y = __shfl_up_sync(0xffffffffu, w, o);
            if (lane >= o) w += y;
        }
        ws[lane] = w;
    }
    __syncthreads();
    int excl = x - tsum + (wid > 0 ? ws[wid - 1] : 0);
    if (base + 0 < N) off[base + 0] = excl;
    if (base + 1 < N) off[base + 1] = excl + v0;
    if (base + 2 < N) off[base + 2] = excl + v0 + v1;
    if (base + 3 < N) off[base + 3] = excl + v0 + v1 + v2;
    if (t == 1023) g_bsum[rel][blockIdx.x] = excl + tsum;
}

__global__ void k_scan2() {
    __shared__ int sh[128];
    int rel = blockIdx.y;
    const int nb = 49;
    int t = threadIdx.x;
    int orig = (t < nb) ? g_bsum[rel][t] : 0;
    sh[t] = orig;
    __syncthreads();
    for (int o = 1; o < 128; o <<= 1) {
        int v = (t >= o) ? sh[t - o] : 0;
        __syncthreads();
        sh[t] += v;
        __syncthreads();
    }
    if (t < nb) g_bsum[rel][t] = sh[t] - orig;
}

__global__ void k_scan3() {
    int rel = blockIdx.y;
    int N = (rel == 0) ? N_TX : N_ADDR;
    int i = blockIdx.x * blockDim.x + threadIdx.x;
    if (i >= N) return;
    int o = g_off[rel][i] + g_bsum[rel][i >> 12];
    g_off[rel][i] = o;
    g_cur[rel][i] = o;
    if (i == N - 1) g_off[rel][N] = o + g_cnt[rel][i];
}

// csr selected in device code (host-side __device__ symbol = wrong address)
__global__ void k_scatter_all(const int* __restrict__ s0, const int* __restrict__ d0,
                              const int* __restrict__ s1, const int* __restrict__ d1,
                              const int* __restrict__ s2, const int* __restrict__ d2) {
    int e = blockIdx.x * blockDim.x + threadIdx.x;
    if (e < E_AT) {
        int p = atomicAdd(&g_cur[0][d0[e]], 1);
        g_csr0[p] = s0[e];
    } else if (e < E_AT + E_TA) {
        int i = e - E_AT;
        int p = atomicAdd(&g_cur[1][d1[i]], 1);
        g_csr1[p] = s1[i];
    } else if (e < E_TOT) {
        int i = e - E_AT - E_TA;
        int p = atomicAdd(&g_cur[2][d2[i]], 1);
        g_csr2[p] = s2[i];
    }
}

// ---------------- per-layer kernels ----------------

// fused: [mix of previous layer (l>0)] + projection (both types) + attention
// dot products. x rows staged through smem (coalesced loads, padded stride 17
// -> conflict-free group reads). 32 nodes/block, 4 nodes/warp, 8 lanes/node,
// lane owns a float4 of output channels (16 FFMA per smem read).
__global__ void k_proj_all(const float* __restrict__ xa, const float* __restrict__ xt,
                           int useExt,
                           const float* __restrict__ Wa, const float* __restrict__ ba,
                           const float* __restrict__ Wt, const float* __restrict__ bt,
                           const float* __restrict__ asl, const float* __restrict__ adl,
                           int F4, int f4sh) {
    __shared__ float4 sWa[64 * 8], sWt[64 * 8];
    __shared__ float4 sx[PROJ_NPB * 17];
    __shared__ float4 sba4[8], sbt4[8], sv4[6][8];
    int tid = threadIdx.x;
    int Wn = (F4 << 2) * 8;
    for (int i = tid; i < Wn; i += blockDim.x) {
        sWa[i] = ((const float4*)Wa)[i];
        sWt[i] = ((const float4*)Wt)[i];
    }
    if (tid < 8) {
        sba4[tid] = ((const float4*)ba)[tid];
        sbt4[tid] = ((const float4*)bt)[tid];
    }
    if (tid < 48) {
        int r = tid >> 3, cc = tid & 7;
        const float* p = (r == 0) ? asl : (r == 1) ? asl + 64 :
                         (r == 2) ? adl + 32 : (r == 3) ? adl + 64 :
                         (r == 4) ? asl + 32 : adl;
        sv4[r][cc] = ((const float4*)p)[cc];
    }

    // stage x rows (fusing the semantic mix for internal layers)
    int nbase = blockIdx.x * PROJ_NPB;
    float a0 = 0.f, a1 = 0.f;
    if (!useExt) { a0 = g_attn[0]; a1 = g_attn[1]; }
    int items = PROJ_NPB << f4sh;
    for (int i = tid; i < items; i += blockDim.x) {
        int row = i >> f4sh, k4 = i & (F4 - 1);
        int node = nbase + row;
        if (node < NODES) {
            bool iA = node < N_ADDR;
            int n = iA ? node : node - N_ADDR;
            float4 v;
            if (useExt) {
                v = ((const float4*)(iA ? xa : xt))[((size_t)n << f4sh) + k4];
            } else if (iA) {
                float4 u = ((const float4*)g_oa1)[(size_t)n * 8 + k4];
                float4 w = ((const float4*)g_oa2)[(size_t)n * 8 + k4];
                v = make_float4(fmaxf(a0 * u.x + a1 * w.x, 0.f),
                                fmaxf(a0 * u.y + a1 * w.y, 0.f),
                                fmaxf(a0 * u.z + a1 * w.z, 0.f),
                                fmaxf(a0 * u.w + a1 * w.w, 0.f));
            } else {
                v = ((const float4*)g_t)[(size_t)n * 8 + k4];
            }
            sx[row * 17 + k4] = v;
        }
    }
    __syncthreads();

    int lane = tid & 31;
    int g = lane >> 3, c4 = lane & 7;
    int lrow = (tid >> 5) * 4 + g;
    int node = nbase + lrow;
    if (node >= NODES) return;   // group-uniform (nodes per group uniform)
    bool isA = node < N_ADDR;
    int n = isA ? node : node - N_ADDR;

    const float4* sW = isA ? sWa : sWt;
    float4 acc = isA ? sba4[c4] : sbt4[c4];
    const float4* xr = sx + lrow * 17;
    for (int k4 = 0; k4 < F4; k4++) {
        float4 xv = xr[k4];
        float4 w0 = sW[(4 * k4 + 0) * 8 + c4];
        float4 w1 = sW[(4 * k4 + 1) * 8 + c4];
        float4 w2 = sW[(4 * k4 + 2) * 8 + c4];
        float4 w3 = sW[(4 * k4 + 3) * 8 + c4];
        acc.x += xv.x * w0.x + xv.y * w1.x + xv.z * w2.x + xv.w * w3.x;
        acc.y += xv.x * w0.y + xv.y * w1.y + xv.z * w2.y + xv.w * w3.y;
        acc.z += xv.x * w0.z + xv.y * w1.z + xv.z * w2.z + xv.w * w3.z;
        acc.w += xv.x * w0.w + xv.y * w1.w + xv.z * w2.w + xv.w * w3.w;
    }
    ((float4*)((isA ? g_ha : g_ht) + (size_t)n * HID))[c4] = acc;

    // attention dot products: lane holds channels 4*c4..4*c4+3; head = c4>>1.
    float4 s0 = sv4[isA ? 0 : 4][c4];
    float4 s1 = sv4[isA ? 1 : 5][c4];
    float p0 = acc.x * s0.x + acc.y * s0.y + acc.z * s0.z + acc.w * s0.w;
    float p1 = acc.x * s1.x + acc.y * s1.y + acc.z * s1.z + acc.w * s1.w;
    float p2 = 0.f, p3 = 0.f;
    if (isA) {
        float4 s2 = sv4[2][c4], s3 = sv4[3][c4];
        p2 = acc.x * s2.x + acc.y * s2.y + acc.z * s2.z + acc.w * s2.w;
        p3 = acc.x * s3.x + acc.y * s3.y + acc.z * s3.z + acc.w * s3.w;
    }
    p0 += __shfl_xor_sync(0xffffffffu, p0, 1);
    p1 += __shfl_xor_sync(0xffffffffu, p1, 1);
    p2 += __shfl_xor_sync(0xffffffffu, p2, 1);
    p3 += __shfl_xor_sync(0xffffffffu, p3, 1);
    if ((c4 & 1) == 0) {
        int h = c4 >> 1;
        if (isA) {
            g_asA0[(size_t)n * 4 + h] = p0;
            g_asA2[(size_t)n * 4 + h] = p1;
            g_adA1[(size_t)n * 4 + h] = p2;
            g_adA2[(size_t)n * 4 + h] = p3;
        } else {
            g_asT[(size_t)n * 4 + h] = p0;
            g_adT[(size_t)n * 4 + h] = p1;
        }
    }
}

// global per-head max of alpha_src per relation (softmax upper bound)
__global__ void k_amax() {
    int r = blockIdx.y;
    const float4* A; int N;
    if (r == 0)      { A = (const float4*)g_asA0; N = N_ADDR; }
    else if (r == 1) { A = (const float4*)g_asT;  N = N_TX; }
    else             { A = (const float4*)g_asA2; N = N_ADDR; }
    const float NEG = __int_as_float(0xff800000);
    float4 m = make_float4(NEG, NEG, NEG, NEG);
    for (int i = blockIdx.x * blockDim.x + threadIdx.x; i < N;
         i += gridDim.x * blockDim.x) {
        float4 v = A[i];
        m.x = fmaxf(m.x, v.x); m.y = fmaxf(m.y, v.y);
        m.z = fmaxf(m.z, v.z); m.w = fmaxf(m.w, v.w);
    }
#pragma unroll
    for (int o = 16; o > 0; o >>= 1) {
        m.x = fmaxf(m.x, __shfl_xor_sync(0xffffffffu, m.x, o));
        m.y = fmaxf(m.y, __shfl_xor_sync(0xffffffffu, m.y, o));
        m.z = fmaxf(m.z, __shfl_xor_sync(0xffffffffu, m.z, o));
        m.w = fmaxf(m.w, __shfl_xor_sync(0xffffffffu, m.w, o));
    }
    __shared__ float4 sm[8];
    int lane = threadIdx.x & 31, wid = threadIdx.x >> 5;
    if (lane == 0) sm[wid] = m;
    __syncthreads();
    if (threadIdx.x < 8) {
        float4 v = sm[threadIdx.x];
#pragma unroll
        for (int o = 4; o > 0; o >>= 1) {
            v.x = fmaxf(v.x, __shfl_xor_sync(0xffu, v.x, o));
            v.y = fmaxf(v.y, __shfl_xor_sync(0xffu, v.y, o));
            v.z = fmaxf(v.z, __shfl_xor_sync(0xffu, v.z, o));
            v.w = fmaxf(v.w, __shfl_xor_sync(0xffu, v.w, o));
        }
        if (threadIdx.x == 0) {
            atomicMax(&g_gmax[r * 4 + 0], fenc(v.x));
            atomicMax(&g_gmax[r * 4 + 1], fenc(v.y));
            atomicMax(&g_gmax[r * 4 + 2], fenc(v.z));
            atomicMax(&g_gmax[r * 4 + 3], fenc(v.w));
        }
    }
}

// fused gather aggregation, all 3 relations. 4 nodes/warp, 8 lanes/node;
// each lane owns one float4 of channels for the whole node -> no cross-lane
// reduction; per-head ssum computed redundantly per lane. Group-masked shfl
// broadcasts prefetched neighbor ids.
__global__ void k_agg_all() {
    int warp = blockIdx.x * (blockDim.x >> 5) + (threadIdx.x >> 5);
    int lane = threadIdx.x & 31;
    int g = lane >> 3, c4 = lane & 7, h = c4 >> 1;
    int vn = warp * 4 + g;
    if (vn >= W_TOT) return;
    int rel, node;
    if (vn < N_TX) { rel = 0; node = vn; }
    else if (vn < N_TX + N_ADDR) { rel = 1; node = vn - N_TX; }
    else { rel = 2; node = vn - N_TX - N_ADDR; }

    const int* off; const int* csr; const float* as_; const float* ad_;
    const float* hs; float* outp;
    if (rel == 0)      { off = g_off[0]; csr = g_csr0; as_ = g_asA0; ad_ = g_adT;  hs = g_ha; outp = g_t; }
    else if (rel == 1) { off = g_off[1]; csr = g_csr1; as_ = g_asT;  ad_ = g_adA1; hs = g_ht; outp = g_oa1; }
    else               { off = g_off[2]; csr = g_csr2; as_ = g_asA2; ad_ = g_adA2; hs = g_ha; outp = g_oa2; }

    int start = off[node], end = off[node + 1];
    float4 res = make_float4(0.f, 0.f, 0.f, 0.f);
    if (start < end) {
        float adv = ad_[(size_t)node * 4 + h];
        float m = lrelu(fdec(g_gmax[rel * 4 + h]) + adv);  // >= all edge logits
        unsigned gm = 0xFFu << (g * 8);
        float4 acc = make_float4(0.f, 0.f, 0.f, 0.f);
        float ssum = 0.f;
        for (int base = start; base < end; base += 8) {
            int nrem = min(8, end - base);
            int idx = (c4 < nrem) ? csr[base + c4] : 0;
            for (int j = 0; j < nrem; j++) {
                int s = __shfl_sync(gm, idx, g * 8 + j);
                float a = as_[(size_t)s * 4 + h];
                float w = __expf(lrelu(a + adv) - m);
                float4 f = ((const float4*)(hs + (size_t)s * HID))[c4];
                acc.x += w * f.x; acc.y += w * f.y;
                acc.z += w * f.z; acc.w += w * f.w;
                ssum += w;
            }
        }
        float inv = 1.f / (ssum + 1e-16f);
        res = make_float4(fmaxf(acc.x * inv, 0.f), fmaxf(acc.y * inv, 0.f),
                          fmaxf(acc.z * inv, 0.f), fmaxf(acc.w * inv, 0.f));
    }
    ((float4*)(outp + (size_t)node * HID))[c4] = res;
}

// semantic accumulation: warp per node (coalesced), lane = channel.
__global__ void k_semacc(const float* __restrict__ kWl, const float* __restrict__ kbl) {
    int r = blockIdx.y;
    const float* O = (r == 0) ? (const float*)g_oa1 : (const float*)g_oa2;
    __shared__ float sW[HID * HID];
    __shared__ float sb_[HID];
    __shared__ float red[HID];
    int tid = threadIdx.x, lane = tid & 31, wid = tid >> 5;
    for (int i = tid; i < HID * HID; i += blockDim.x) sW[i] = kWl[i];
    if (tid < HID) { sb_[tid] = kbl[tid]; red[tid] = 0.f; }
    __syncthreads();

    float acc = 0.f;
    int wstride = gridDim.x * (blockDim.x >> 5);
    for (int n = blockIdx.x * (blockDim.x >> 5) + wid; n < N_ADDR; n += wstride) {
        float x = O[(size_t)n * HID + lane];
        float dsum = sb_[lane];
#pragma unroll
        for (int k = 0; k < HID; k++)
            dsum += __shfl_sync(0xffffffffu, x, k) * sW[k * HID + lane];
        acc += tanhf(dsum);
    }
    atomicAdd(&red[lane], acc);
    __syncthreads();
    if (tid < HID) atomicAdd(&g_sem[r * HID + tid], red[tid]);
}

// softmax over 2 relation scores; resets g_sem/g_gmax for next layer/replay
__global__ void k_attn(const float* __restrict__ q) {
    int c = threadIdx.x;
    const float inv = 1.0f / (float)N_ADDR;
    float qc = q[c];
    float p0 = g_sem[c] * inv * qc;
    float p1 = g_sem[HID + c] * inv * qc;
    for (int o = 16; o > 0; o >>= 1) {
        p0 += __shfl_xor_sync(0xffffffffu, p0, o);
        p1 += __shfl_xor_sync(0xffffffffu, p1, o);
    }
    if (c == 0) {
        float m = fmaxf(p0, p1);
        float e0 = __expf(p0 - m), e1 = __expf(p1 - m);
        float is = 1.f / (e0 + e1);
        g_attn[0] = e0 * is;
        g_attn[1] = e1 * is;
    }
    __syncwarp();
    g_sem[c] = 0.f;
    g_sem[HID + c] = 0.f;
    if (c < 3 * HEADS) g_gmax[c] = 0u;
}

// final linear with fused semantic mix: warp per node, shfl reduce.
__global__ void k_lin(const float* __restrict__ linW, const float* __restrict__ linb,
                      float* __restrict__ out) {
    int gw = blockIdx.x * (blockDim.x >> 5) + (threadIdx.x >> 5);
    int c = threadIdx.x & 31;
    if (gw >= N_ADDR) return;
    float a0 = g_attn[0], a1 = g_attn[1];
    float v = fmaxf(a0 * g_oa1[(size_t)gw * HID + c] +
                    a1 * g_oa2[(size_t)gw * HID + c], 0.f);
    float s0 = v * linW[c * 2];
    float s1 = v * linW[c * 2 + 1];
#pragma unroll
    for (int o = 16; o > 0; o >>= 1) {
        s0 += __shfl_xor_sync(0xffffffffu, s0, o);
        s1 += __shfl_xor_sync(0xffffffffu, s1, o);
    }
    if (c == 0)
        *(float2*)(out + (size_t)gw * 2) = make_float2(s0 + linb[0], s1 + linb[1]);
}

// ---------------- host ----------------
extern "C" void kernel_launch(void* const* d_in, const int* in_sizes, int n_in,
                              void* d_out, int out_size) {
    const float* x_addr  = (const float*)d_in[0];
    const float* x_tx    = (const float*)d_in[1];
    const int*   eat_s   = (const int*)d_in[2];
    const int*   eat_d   = (const int*)d_in[3];
    const int*   eta_s   = (const int*)d_in[4];
    const int*   eta_d   = (const int*)d_in[5];
    const int*   eaa_s   = (const int*)d_in[6];
    const int*   eaa_d   = (const int*)d_in[7];
    const float* pW1     = (const float*)d_in[8];
    const float* pb1     = (const float*)d_in[9];
    const float* pW23    = (const float*)d_in[10];
    const float* pb23    = (const float*)d_in[11];
    const float* att_src = (const float*)d_in[12];
    const float* att_dst = (const float*)d_in[13];
    const float* kW      = (const float*)d_in[14];
    const float* kb      = (const float*)d_in[15];
    const float* q       = (const float*)d_in[16];
    const float* linW    = (const float*)d_in[17];
    const float* linb    = (const float*)d_in[18];
    float* out = (float*)d_out;

    const int B = 256;
    const int PROJ_BLK = cdiv(NODES, PROJ_NPB);
    const int AGG_BLK = cdiv(W_TOT / 4, 8);   // 4 nodes/warp, 8 warps/block

    // ---- CSR build (once); layer-0 proj interleaved (independent) ----
    k_zero_cnt<<<cdiv(N_TX, B), B>>>();
    k_hist_all<<<cdiv(E_TOT, B), B>>>(eat_d, eta_d, eaa_d);
    k_scan1<<<dim3(49, 3), 1024>>>();
    k_proj_all<<<PROJ_BLK, B>>>(x_addr, x_tx, 1,
                                pW1, pb1, pW1 + 64 * HID, pb1 + HID,
                                att_src, att_dst, 16, 4);
    k_scan2<<<dim3(1, 3), 128>>>();
    k_scan3<<<dim3(cdiv(N_TX, B), 3), B>>>();
    k_scatter_all<<<cdiv(E_TOT, B), B>>>(eat_s, eat_d, eta_s, eta_d, eaa_s, eaa_d);

    // ---- layers ----
    for (int l = 0; l < 3; l++) {
        if (l > 0) {
            const float* Wa = pW23 + (size_t)(l - 1) * 2 * HID * HID;
            const float* ba = pb23 + (size_t)(l - 1) * 2 * HID;
            k_proj_all<<<PROJ_BLK, B>>>(x_addr, x_tx, 0,
                                        Wa, ba, Wa + HID * HID, ba + HID,
                                        att_src + l * 96, att_dst + l * 96, 8, 3);
        }
        k_amax<<<dim3(64, 3), B>>>();
        k_agg_all<<<AGG_BLK, B>>>();
        k_semacc<<<dim3(148, 2), B>>>(kW + (size_t)l * HID * HID, kb + l * HID);
        k_attn<<<1, 32>>>(q + l * HID);
    }
    k_lin<<<cdiv(N_ADDR, 8), B>>>(linW, linb, out);
}